// round 11
// baseline (speedup 1.0000x reference)
#include <cuda_runtime.h>
#include <cuda_bf16.h>
#include <cstdint>

// ---------------------------------------------------------------------------
// MaskedCrossAttention — round 11: attention occupancy push.
//  * 64-key inner blocks: acc[8][4] (half the regs), smem 48KB, 3 CTAs/SM
//    via __launch_bounds__(128,3). Online softmax per 64-key block.
//  * GEMMs / packs identical to round 10.
// bf16 hi/lo split math: D = AhBh + AhBl + AlBh (err ~1.8e-5).
// ---------------------------------------------------------------------------

#define BATCH   2
#define TTEXT   2048
#define DIM_    1024
#define TMEDIA  8
#define MTOK    256
#define HEADS   16
#define DHEAD   64
#define INNER   1024
#define NROWS   (BATCH * TTEXT)
#define KVROWS  (BATCH * TMEDIA * MTOK)
#define SCALE_  0.125f
#define KDIM    1024

// ------------------------------- scratch ----------------------------------
__device__ unsigned int g_xnp   [NROWS  * KDIM];
__device__ unsigned int g_medp  [KVROWS * KDIM];
__device__ unsigned int g_aop   [NROWS  * KDIM];
__device__ unsigned int g_wqt   [INNER      * KDIM];
__device__ unsigned int g_wkvt  [2 * INNER  * KDIM];
__device__ unsigned int g_woutt [DIM_       * KDIM];
__device__ unsigned int g_qp    [NROWS  * INNER];
__device__ unsigned int g_kvp   [KVROWS * 2 * INNER];
__device__ int          g_tt[NROWS];

// --------------------------- helpers ---------------------------------------
__device__ __forceinline__ uint32_t smem_u32(const void* p) {
    uint32_t a;
    asm("{ .reg .u64 t; cvta.to.shared.u64 t, %1; cvt.u32.u64 %0, t; }" : "=r"(a) : "l"(p));
    return a;
}
#define SWZ128(o) ((o) ^ (((o) >> 3) & 0x70))

#define CP_ASYNC16(dst, src) \
    asm volatile("cp.async.cg.shared.global [%0], [%1], 16;" :: "r"(dst), "l"(src) : "memory")
#define CP_COMMIT() asm volatile("cp.async.commit_group;" ::: "memory")
#define CP_WAIT0()  asm volatile("cp.async.wait_group 0;" ::: "memory")
#define CP_WAIT1()  asm volatile("cp.async.wait_group 1;" ::: "memory")

#define LDSM4(r, addr)                                                        \
    asm volatile("ldmatrix.sync.aligned.m8n8.x4.shared.b16 {%0,%1,%2,%3}, [%4];" \
        : "=r"((r)[0]), "=r"((r)[1]), "=r"((r)[2]), "=r"((r)[3]) : "r"(addr))

#define MMA16816(d, a, b)                                                     \
    asm volatile("mma.sync.aligned.m16n8k16.row.col.f32.bf16.bf16.f32 "       \
        "{%0,%1,%2,%3}, {%4,%5,%6,%7}, {%8,%9}, {%0,%1,%2,%3};"               \
        : "+f"((d)[0]), "+f"((d)[1]), "+f"((d)[2]), "+f"((d)[3])              \
        : "r"((a)[0]), "r"((a)[1]), "r"((a)[2]), "r"((a)[3]),                 \
          "r"((b)[0]), "r"((b)[1]))

#define STS32(addr, v) asm volatile("st.shared.u32 [%0], %1;" :: "r"(addr), "r"(v) : "memory")

// ----------------------------- split helpers --------------------------------
__device__ __forceinline__ unsigned int bfpack2(float a, float b, float& ra, float& rb) {
    __nv_bfloat16 ha = __float2bfloat16(a), hb = __float2bfloat16(b);
    ra = a - __bfloat162float(ha);
    rb = b - __bfloat162float(hb);
    unsigned short xa = ((__nv_bfloat16_raw)ha).x, xb = ((__nv_bfloat16_raw)hb).x;
    return (unsigned int)xa | ((unsigned int)xb << 16);
}
__device__ __forceinline__ unsigned int bfpack2n(float a, float b) {
    __nv_bfloat16 ha = __float2bfloat16(a), hb = __float2bfloat16(b);
    unsigned short xa = ((__nv_bfloat16_raw)ha).x, xb = ((__nv_bfloat16_raw)hb).x;
    return (unsigned int)xa | ((unsigned int)xb << 16);
}
__device__ __forceinline__ void split4(float4 v, uint2& H, uint2& L) {
    float r0, r1, r2, r3;
    H.x = bfpack2(v.x, v.y, r0, r1);
    H.y = bfpack2(v.z, v.w, r2, r3);
    L.x = bfpack2n(r0, r1);
    L.y = bfpack2n(r2, r3);
}

// --------------------------- text_time cumsum -----------------------------
__global__ void k_texttime(const unsigned char* __restrict__ locs_raw,
                           int* __restrict__ tt) {
    int b = blockIdx.x;
    int lane = threadIdx.x;
    int cnt = 0;
    for (int i = lane; i < BATCH * TTEXT; i += 32) cnt += (locs_raw[i] != 0);
    #pragma unroll
    for (int off = 16; off; off >>= 1) cnt += __shfl_xor_sync(0xffffffffu, cnt, off);
    bool bytemode = (cnt >= 12);

    const int seg = TTEXT / 32;
    int base = b * TTEXT + lane * seg;
    int s = 0;
    if (bytemode) { for (int i = 0; i < seg; i++) s += (locs_raw[base + i] != 0); }
    else { const int* li = (const int*)locs_raw; for (int i = 0; i < seg; i++) s += (li[base + i] != 0); }
    int inc = s;
    #pragma unroll
    for (int off = 1; off < 32; off <<= 1) {
        int v = __shfl_up_sync(0xffffffffu, inc, off);
        if (lane >= off) inc += v;
    }
    int run = inc - s;
    int* o = tt + base;
    if (bytemode) { for (int i = 0; i < seg; i++) { run += (locs_raw[base + i] != 0); o[i] = run; } }
    else { const int* li = (const int*)locs_raw; for (int i = 0; i < seg; i++) { run += (li[base + i] != 0); o[i] = run; } }
}

// --------------------- fused pack: LN rows + media rows + weights -----------
__device__ __forceinline__ void wpack_tile(const float* __restrict__ W,
                                           unsigned int* __restrict__ out,
                                           int N, int bx, int by) {
    __shared__ float t[32][33];
    int tid = threadIdx.x;
    int k0 = by * 32, n0 = bx * 32;
    {
        int kr = tid >> 3, f4 = (tid & 7) * 4;
        float4 v = *(const float4*)&W[(size_t)(k0 + kr) * N + n0 + f4];
        t[f4 + 0][kr] = v.x; t[f4 + 1][kr] = v.y; t[f4 + 2][kr] = v.z; t[f4 + 3][kr] = v.w;
    }
    __syncthreads();
    {
        int n = tid >> 3, kq = (tid & 7) * 4;
        float4 u = make_float4(t[n][kq], t[n][kq + 1], t[n][kq + 2], t[n][kq + 3]);
        uint2 H, L;
        split4(u, H, L);
        size_t idx = (size_t)(n0 + n) * KDIM + (k0 >> 5) * 32 + (kq >> 1);
        *(uint2*)&out[idx]      = H;
        *(uint2*)&out[idx + 16] = L;
    }
}

__global__ __launch_bounds__(256) void k_pack_all(
        const float* __restrict__ x,
        const float* __restrict__ gamma,
        const float* __restrict__ beta,
        const float* __restrict__ media,
        const float* __restrict__ Wq,
        const float* __restrict__ Wkv,
        const float* __restrict__ Wout,
        unsigned int* __restrict__ xnp,
        unsigned int* __restrict__ medp,
        unsigned int* __restrict__ wqt,
        unsigned int* __restrict__ wkvt,
        unsigned int* __restrict__ woutt) {
    int bid = blockIdx.x;
    int tid = threadIdx.x;
    if (bid < NROWS) {
        int row = bid;
        const float4* xr = (const float4*)(x + (size_t)row * DIM_);
        float4 v = xr[tid];
        float s = v.x + v.y + v.z + v.w;
        float q = v.x * v.x + v.y * v.y + v.z * v.z + v.w * v.w;
        __shared__ float ss[8], sq[8];
        #pragma unroll
        for (int off = 16; off; off >>= 1) {
            s += __shfl_xor_sync(0xffffffffu, s, off);
            q += __shfl_xor_sync(0xffffffffu, q, off);
        }
        int w = tid >> 5, l = tid & 31;
        if (l == 0) { ss[w] = s; sq[w] = q; }
        __syncthreads();
        if (w == 0) {
            s = (l < 8) ? ss[l] : 0.f;
            q = (l < 8) ? sq[l] : 0.f;
            #pragma unroll
            for (int off = 4; off; off >>= 1) {
                s += __shfl_xor_sync(0xffffffffu, s, off);
                q += __shfl_xor_sync(0xffffffffu, q, off);
            }
            if (l == 0) { ss[0] = s; sq[0] = q; }
        }
        __syncthreads();
        float mu   = ss[0] * (1.0f / DIM_);
        float var  = sq[0] * (1.0f / DIM_) - mu * mu;
        float rstd = rsqrtf(var + 1e-5f);
        float4 g  = ((const float4*)gamma)[tid];
        float4 bb = ((const float4*)beta)[tid];
        float4 o;
        o.x = (v.x - mu) * rstd * g.x + bb.x;
        o.y = (v.y - mu) * rstd * g.y + bb.y;
        o.z = (v.z - mu) * rstd * g.z + bb.z;
        o.w = (v.w - mu) * rstd * g.w + bb.w;
        uint2 H, L;
        split4(o, H, L);
        size_t idx = (size_t)row * KDIM + (tid >> 3) * 32 + (tid & 7) * 2;
        *(uint2*)&xnp[idx]      = H;
        *(uint2*)&xnp[idx + 16] = L;
    } else if (bid < NROWS + KVROWS) {
        int row = bid - NROWS;
        float4 v = ((const float4*)(media + (size_t)row * KDIM))[tid];
        uint2 H, L;
        split4(v, H, L);
        size_t idx = (size_t)row * KDIM + (tid >> 3) * 32 + (tid & 7) * 2;
        *(uint2*)&medp[idx]      = H;
        *(uint2*)&medp[idx + 16] = L;
    } else {
        int wb = bid - (NROWS + KVROWS);
        if (wb < 1024) {
            wpack_tile(Wq, wqt, INNER, wb & 31, wb >> 5);
        } else if (wb < 3072) {
            int b2 = wb - 1024;
            wpack_tile(Wkv, wkvt, 2 * INNER, b2 & 63, b2 >> 6);
        } else {
            int b3 = wb - 3072;
            wpack_tile(Wout, woutt, DIM_, b3 & 31, b3 >> 5);
        }
    }
}

// --------------------- warp-MMA split-bf16 GEMM body ------------------------
#define GSTAGE_B   32768
#define GSTAGES    3
#define STAGE_ROWB 528
#define GSMEM      (GSTAGES * GSTAGE_B)

template <bool PACK>
__device__ __forceinline__ void gemm_body(const uint4* __restrict__ A,
                                          const uint4* __restrict__ B,
                                          void* __restrict__ Cout,
                                          int N, int bx, int by, char* sm) {
    const int tid = threadIdx.x, wid = tid >> 5, lane = tid & 31;
    const uint32_t smb = smem_u32(sm);
    const int rowb = by * 128, colb = bx * 128;
    const int warp_m = wid >> 2, warp_n = wid & 3;
    const int r = tid >> 3, sgi = tid & 7;
    const uint4* Ab = A + (size_t)rowb * 256;
    const uint4* Bb = B + (size_t)colb * 256;

    const int arow_l = (lane & 7) + ((lane >> 3) & 1) * 8;
    const int acol_l = (lane >> 4) * 16;
    const int brow_l = (lane & 7) + (lane >> 4) * 8;
    const int bcol_l = ((lane >> 3) & 1) * 16;

    float acc[4][4][4];
    #pragma unroll
    for (int mt = 0; mt < 4; mt++)
        #pragma unroll
        for (int nt = 0; nt < 4; nt++)
            #pragma unroll
            for (int e = 0; e < 4; e++) acc[mt][nt][e] = 0.f;

    #pragma unroll
    for (int c0 = 0; c0 < 2; c0++) {
        uint32_t stp = smb + c0 * GSTAGE_B;
        #pragma unroll
        for (int it = 0; it < 4; it++) {
            int rr = r + it * 32;
            uint32_t so = SWZ128(rr * 128 + sgi * 16);
            CP_ASYNC16(stp + so,         (const void*)(Ab + (size_t)rr * 256 + c0 * 8 + sgi));
            CP_ASYNC16(stp + 16384 + so, (const void*)(Bb + (size_t)rr * 256 + c0 * 8 + sgi));
        }
        CP_COMMIT();
    }
    CP_WAIT1();
    __syncthreads();

    for (int c = 0; c < 32; c++) {
        uint32_t stb = smb + (c % GSTAGES) * GSTAGE_B;
        if (c + 2 < 32) {
            uint32_t nstb = smb + ((c + 2) % GSTAGES) * GSTAGE_B;
            #pragma unroll
            for (int it = 0; it < 4; it++) {
                int rr = r + it * 32;
                uint32_t so = SWZ128(rr * 128 + sgi * 16);
                CP_ASYNC16(nstb + so,         (const void*)(Ab + (size_t)rr * 256 + (c + 2) * 8 + sgi));
                CP_ASYNC16(nstb + 16384 + so, (const void*)(Bb + (size_t)rr * 256 + (c + 2) * 8 + sgi));
            }
            CP_COMMIT();
        }

        #pragma unroll
        for (int s = 0; s < 2; s++) {
            const int kbh = s * 32, kbl = 64 + s * 32;
            uint32_t bh[2][4], bl[2][4];
            #pragma unroll
            for (int p = 0; p < 2; p++) {
                int bb = 16384 + (warp_n * 32 + p * 16 + brow_l) * 128 + bcol_l;
                LDSM4(bh[p], stb + SWZ128(bb + kbh));
                LDSM4(bl[p], stb + SWZ128(bb + kbl));
            }
            #pragma unroll
            for (int mt = 0; mt < 4; mt++) {
                uint32_t ah[4], al[4];
                int ab = (warp_m * 64 + mt * 16 + arow_l) * 128 + acol_l;
                LDSM4(ah, stb + SWZ128(ab + kbh));
                LDSM4(al, stb + SWZ128(ab + kbl));
                #pragma unroll
                for (int nt = 0; nt < 4; nt++) {
                    MMA16816(acc[mt][nt], ah, &bh[nt >> 1][(nt & 1) * 2]);
                    MMA16816(acc[mt][nt], ah, &bl[nt >> 1][(nt & 1) * 2]);
                    MMA16816(acc[mt][nt], al, &bh[nt >> 1][(nt & 1) * 2]);
                }
            }
        }
        if (c + 1 < 32) {
            if (c + 2 < 32) { CP_WAIT1(); } else { CP_WAIT0(); }
        }
        __syncthreads();
    }

    #pragma unroll
    for (int mt = 0; mt < 4; mt++) {
        #pragma unroll
        for (int hf = 0; hf < 2; hf++) {
            int r0 = warp_m * 64 + mt * 16 + hf * 8 + (lane >> 2);
            #pragma unroll
            for (int nt = 0; nt < 4; nt++) {
                int cl = warp_n * 32 + nt * 8 + (lane & 3) * 2;
                if (PACK) {
                    float rr0, rr1;
                    unsigned int hi = bfpack2(acc[mt][nt][hf * 2], acc[mt][nt][hf * 2 + 1], rr0, rr1);
                    unsigned int lo = bfpack2n(rr0, rr1);
                    int wl = (cl >> 5) * 32 + ((cl & 31) >> 1);
                    *(unsigned int*)(sm + r0 * STAGE_ROWB + wl * 4)      = hi;
                    *(unsigned int*)(sm + r0 * STAGE_ROWB + wl * 4 + 64) = lo;
                } else {
                    *(float2*)(sm + r0 * STAGE_ROWB + cl * 4) =
                        make_float2(acc[mt][nt][hf * 2], acc[mt][nt][hf * 2 + 1]);
                }
            }
        }
    }
    __syncthreads();
    char* Cb = (char*)Cout;
    #pragma unroll
    for (int i = 0; i < 16; i++) {
        int idx = tid + i * 256;
        int row = idx >> 5, ch = idx & 31;
        uint4 v = *(uint4*)(sm + row * STAGE_ROWB + ch * 16);
        *(uint4*)(Cb + ((size_t)(rowb + row) * N + colb + ch * 4) * 4) = v;
    }
}

__global__ __launch_bounds__(256, 2) void k_gemm_qkv(const uint4* __restrict__ Aq,
                                                     const uint4* __restrict__ Bq,
                                                     unsigned int* __restrict__ Cq,
                                                     const uint4* __restrict__ Akv,
                                                     const uint4* __restrict__ Bkv,
                                                     unsigned int* __restrict__ Ckv) {
    extern __shared__ __align__(1024) char sm[];
    int bid = blockIdx.x;
    if (bid < 256) {
        gemm_body<true>(Aq, Bq, Cq, INNER, bid & 7, bid >> 3, sm);
    } else {
        int b2 = bid - 256;
        gemm_body<true>(Akv, Bkv, Ckv, 2 * INNER, b2 & 15, b2 >> 4, sm);
    }
}

__global__ __launch_bounds__(256, 2) void k_gemm_out(const uint4* __restrict__ A,
                                                     const uint4* __restrict__ B,
                                                     float* __restrict__ C) {
    extern __shared__ __align__(1024) char sm[];
    int bid = blockIdx.x;
    gemm_body<false>(A, B, C, DIM_, bid & 7, bid >> 3, sm);
}

// ------------------------- attention (FA2-style, 64-key blocks) -------------
// grid (64 q-tiles, 16 heads); block 128 (4 warps, M-split 16 rows/warp).
// Keys per chunk processed in four 64-key blocks with online softmax.
// SMEM: Q 2x8192 @0 | K 2x8192 @16384 | VT 2x8192 @32768 | Ts @49152.
#define ATT_Q    0
#define ATT_K    16384
#define ATT_VT   32768
#define ATT_TS   49152
#define ATT_SMEM (ATT_TS + 256)

__global__ __launch_bounds__(128, 3) void k_attn(const unsigned int* __restrict__ qp,
                                                 const unsigned int* __restrict__ kvp,
                                                 const int* __restrict__ tt,
                                                 unsigned int* __restrict__ aop) {
    extern __shared__ __align__(1024) char sm[];
    const uint32_t smb = smem_u32(sm);
    const int tid = threadIdx.x, w = tid >> 5, lane = tid & 31;
    const int tile = blockIdx.x, h = blockIdx.y;
    const int gq0 = tile * 64;
    const int b = gq0 >> 11;

    const int arow_l = (lane & 7) + ((lane >> 3) & 1) * 8;
    const int acol_l = (lane >> 4) * 16;
    const int brow_l = (lane & 7) + (lane >> 4) * 8;
    const int bcol_l = ((lane >> 3) & 1) * 16;

    int* Ts = (int*)(sm + ATT_TS);
    if (tid < 64) Ts[tid] = tt[gq0 + tid];

    // ---- load Q tile once (hi/lo panels), 8 uint4/thread
    #pragma unroll
    for (int it = 0; it < 8; it++) {
        int t = tid + it * 128;
        int row = t >> 4, rest = t & 15;
        int panel = rest >> 3, q4 = rest & 7;
        uint4 v = *(const uint4*)&qp[(size_t)(gq0 + row) * 1024 + (h * 2 + panel) * 32 + q4 * 4];
        *(uint4*)(sm + ATT_Q + panel * 8192 + SWZ128(row * 128 + q4 * 16)) = v;
    }
    __syncthreads();

    // ---- zero rows with text_time == 0 (this head's 64-word segment)
    #pragma unroll
    for (int it = 0; it < 8; it++) {
        int slot = tid + it * 128;
        int row = slot >> 4, w4 = slot & 15;
        if (Ts[row] == 0)
            *(uint4*)&aop[(size_t)(gq0 + row) * 1024 + h * 64 + w4 * 4] =
                make_uint4(0, 0, 0, 0);
    }

    int c0 = Ts[0] < 1 ? 1 : Ts[0];
    int c1 = Ts[63];
    const int rr0 = w * 16 + (lane >> 2);
    const int rr8 = rr0 + 8;

    for (int c = c0; c <= c1; c++) {
        float o[8][4];
        #pragma unroll
        for (int dt = 0; dt < 8; dt++)
            #pragma unroll
            for (int e = 0; e < 4; e++) o[dt][e] = 0.f;
        float pm0 = -1e30f, pm1 = -1e30f, l0 = 0.f, l1 = 0.f;

        #pragma unroll
        for (int kb4 = 0; kb4 < 4; kb4++) {
            const int kbase = b * (TMEDIA * MTOK) + (c - 1) * MTOK + kb4 * 64;
            __syncthreads();   // K/VT free of prior readers
            // ---- load K block (64 keys x 2 panels), 8 uint4/thread
            #pragma unroll
            for (int it = 0; it < 8; it++) {
                int t = tid + it * 128;
                int row = t >> 4, rest = t & 15;
                int panel = rest >> 3, q4 = rest & 7;
                uint4 v = *(const uint4*)&kvp[(size_t)(kbase + row) * 2048 + (h * 2 + panel) * 32 + q4 * 4];
                *(uint4*)(sm + ATT_K + panel * 8192 + SWZ128(row * 128 + q4 * 16)) = v;
            }
            // ---- V^T scatter block (32 token pairs, 32-bit stores), 8 iters
            #pragma unroll
            for (int it = 0; it < 8; it++) {
                int idx = tid + it * 128;
                int tp = idx >> 5, w5 = idx & 31;
                int bbh = w5 >> 4, wi = w5 & 15;
                int k0 = tp * 2;
                size_t srci = (size_t)(kbase + k0) * 2048 + (32 + h * 2 + bbh) * 32 + wi;
                unsigned int hw0 = kvp[srci],      hw1 = kvp[srci + 2048];
                unsigned int lw0 = kvp[srci + 16], lw1 = kvp[srci + 2048 + 16];
                int d0 = bbh * 32 + wi * 2;
                int pnl = k0 >> 5, kl = k0 & 31;
                uint32_t pb = smb + ATT_VT + pnl * 8192;
                STS32(pb + SWZ128(d0 * 128 + kl * 2),            (hw0 & 0xffffu) | (hw1 << 16));
                STS32(pb + SWZ128((d0 + 1) * 128 + kl * 2),      (hw0 >> 16) | (hw1 & 0xffff0000u));
                STS32(pb + SWZ128(d0 * 128 + 64 + kl * 2),       (lw0 & 0xffffu) | (lw1 << 16));
                STS32(pb + SWZ128((d0 + 1) * 128 + 64 + kl * 2), (lw0 >> 16) | (lw1 & 0xffff0000u));
            }
            __syncthreads();

            // ---- QK^T: warp tile M=16, N=64, K=64 (split x3)
            float acc[8][4];
            #pragma unroll
            for (int nt = 0; nt < 8; nt++)
                #pragma unroll
                for (int e = 0; e < 4; e++) acc[nt][e] = 0.f;

            #pragma unroll
            for (int cc = 0; cc < 2; cc++) {
                uint32_t qb = smb + ATT_Q + cc * 8192;
                uint32_t kb = smb + ATT_K + cc * 8192;
                #pragma unroll
                for (int s = 0; s < 2; s++) {
                    const int kbh = s * 32, kbl = 64 + s * 32;
                    uint32_t ah[4], al[4];
                    int ab = (w * 16 + arow_l) * 128 + acol_l;
                    LDSM4(ah, qb + SWZ128(ab + kbh));
                    LDSM4(al, qb + SWZ128(ab + kbl));
                    uint32_t bh[4][4], bl[4][4];
                    #pragma unroll
                    for (int p = 0; p < 4; p++) {
                        int bb = (p * 16 + brow_l) * 128 + bcol_l;
                        LDSM4(bh[p], kb + SWZ128(bb + kbh));
                        LDSM4(bl[p], kb + SWZ128(bb + kbl));
                    }
                    #pragma unroll
                    for (int nt = 0; nt < 8; nt++) {
                        MMA16816(acc[nt], ah, &bh[nt >> 1][(nt & 1) * 2]);
                        MMA16816(acc[nt], ah, &bl[nt >> 1][(nt & 1) * 2]);
                        MMA16816(acc[nt], al, &bh[nt >> 1][(nt & 1) * 2]);
                    }
                }
            }

            // ---- online softmax (warp-local; rows rr0 and rr8)
            float m0 = -1e30f, m1 = -1e30f;
            #pragma unroll
            for (int nt = 0; nt < 8; nt++) {
                acc[nt][0] *= SCALE_; acc[nt][1] *= SCALE_;
                acc[nt][2] *= SCALE_; acc[nt][3] *= SCALE_;
                m0 = fmaxf(m0, fmaxf(acc[nt][0], acc[nt][1]));
                m1 = fmaxf(m1, fmaxf(acc[nt][2], acc[nt][3]));
            }
            m0 = fmaxf(m0, __shfl_xor_sync(0xffffffffu, m0, 1));
            m0 = fmaxf(m0, __shfl_xor_sync(0xffffffffu, m0, 2));
            m1 = fmaxf(m1, __shfl_xor_sync(0xffffffffu, m1, 1));
            m1 = fmaxf(m1, __shfl_xor_sync(0xffffffffu, m1, 2));
            float n0 = fmaxf(pm0, m0), n1 = fmaxf(pm1, m1);
            float a0 = __expf(pm0 - n0), a1 = __expf(pm1 - n1);
            #pragma unroll
            for (int dt = 0; dt < 8; dt++) {
                o[dt][0] *= a0; o[dt][1] *= a0;
                o[dt][2] *= a1; o[dt][3] *= a1;
            }
            float s0 = 0.f, s1 = 0.f;
            #pragma unroll
            for (int nt = 0; nt < 8; nt++) {
                float e0 = __expf(acc[nt][0] - n0), e1 = __expf(acc[nt][1] - n0);
                float e2 = __expf(acc[nt][2] - n1), e3 = __expf(acc[nt][3] - n1);
                acc[nt][0] = e0; acc[nt][1] = e1; acc[nt][2] = e2; acc[nt][3] = e3;
                s0 += e0 + e1; s1 += e2 + e3;
            }
            s0 += __shfl_xor_sync(0xffffffffu, s0, 1);
            s0 += __shfl_xor_sync(0xffffffffu, s0, 2);
            s1 += __shfl_xor_sync(0xffffffffu, s1, 1);
            s1 += __shfl_xor_sync(0xffffffffu, s1, 2);
            l0 = l0 * a0 + s0; l1 = l1 * a1 + s1;
            pm0 = n0; pm1 = n1;

            // ---- PV: P from registers (S frag == A frag), K=64 (split x3)
            #pragma unroll
            for (int ks = 0; ks < 4; ks++) {
                uint32_t aph[4], apl[4];
                float q0, q1;
                aph[0] = bfpack2(acc[2 * ks][0],     acc[2 * ks][1],     q0, q1);
                apl[0] = bfpack2n(q0, q1);
                aph[1] = bfpack2(acc[2 * ks][2],     acc[2 * ks][3],     q0, q1);
                apl[1] = bfpack2n(q0, q1);
                aph[2] = bfpack2(acc[2 * ks + 1][0], acc[2 * ks + 1][1], q0, q1);
                apl[2] = bfpack2n(q0, q1);
                aph[3] = bfpack2(acc[2 * ks + 1][2], acc[2 * ks + 1][3], q0, q1);
                apl[3] = bfpack2n(q0, q1);

                uint32_t vb = smb + ATT_VT + (ks >> 1) * 8192;
                const int kbh = (ks & 1) * 32, kbl = 64 + (ks & 1) * 32;
                uint32_t bvh[4][4], bvl[4][4];
                #pragma unroll
                for (int d16 = 0; d16 < 4; d16++) {
                    int bb = (d16 * 16 + brow_l) * 128 + bcol_l;
                    LDSM4(bvh[d16], vb + SWZ128(bb + kbh));
                    LDSM4(bvl[d16], vb + SWZ128(bb + kbl));
                }
                #pragma unroll
                for (int dt = 0; dt < 8; dt++) {
                    MMA16816(o[dt], aph, &bvh[dt >> 1][(dt & 1) * 2]);
                    MMA16816(o[dt], aph, &bvl[dt >> 1][(dt & 1) * 2]);
                    MMA16816(o[dt], apl, &bvh[dt >> 1][(dt & 1) * 2]);
                }
            }
        }

        // ---- store rows belonging to this chunk (deferred normalization)
        float inv0 = 1.0f / l0, inv1 = 1.0f / l1;
        bool st0 = (Ts[rr0] == c), st1 = (Ts[rr8] == c);
        if (st0 || st1) {
            #pragma unroll
            for (int dt = 0; dt < 8; dt++) {
                int d2 = dt * 8 + (lane & 3) * 2;
                int wofs = (h * 2 + (d2 >> 5)) * 32 + ((d2 & 31) >> 1);
                if (st0) {
                    float q0, q1;
                    unsigned int hi = bfpack2(o[dt][0] * inv0, o[dt][1] * inv0, q0, q1);
                    unsigned int lo = bfpack2n(q0, q1);
                    size_t idx = (size_t)(gq0 + rr0) * 1024 + wofs;
                    aop[idx] = hi; aop[idx + 16] = lo;
                }
                if (st1) {
                    float q0, q1;
                    unsigned int hi = bfpack2(o[dt][2] * inv1, o[dt][3] * inv1, q0, q1);
                    unsigned int lo = bfpack2n(q0, q1);
                    size_t idx = (size_t)(gq0 + rr8) * 1024 + wofs;
                    aop[idx] = hi; aop[idx + 16] = lo;
                }
            }
        }
    }
}

// ------------------------------- launcher ---------------------------------
extern "C" void kernel_launch(void* const* d_in, const int* in_sizes, int n_in,
                              void* d_out, int out_size) {
    const float*         x     = (const float*)d_in[0];
    const float*         media = (const float*)d_in[1];
    const unsigned char* locs  = (const unsigned char*)d_in[2];
    const float*         gamma = (const float*)d_in[3];
    const float*         beta  = (const float*)d_in[4];
    const float*         Wq    = (const float*)d_in[5];
    const float*         Wkv   = (const float*)d_in[6];
    const float*         Wout  = (const float*)d_in[7];
    float*               out   = (float*)d_out;

    unsigned int *xnp, *medp, *aop, *wqt, *wkvt, *woutt, *qp, *kvp;
    int *ttb;
    cudaGetSymbolAddress((void**)&xnp,   g_xnp);
    cudaGetSymbolAddress((void**)&medp,  g_medp);
    cudaGetSymbolAddress((void**)&aop,   g_aop);
    cudaGetSymbolAddress((void**)&wqt,   g_wqt);
    cudaGetSymbolAddress((void**)&wkvt,  g_wkvt);
    cudaGetSymbolAddress((void**)&woutt, g_woutt);
    cudaGetSymbolAddress((void**)&qp,    g_qp);
    cudaGetSymbolAddress((void**)&kvp,   g_kvp);
    cudaGetSymbolAddress((void**)&ttb,   g_tt);

    static bool attr_done = false;
    if (!attr_done) {
        cudaFuncSetAttribute(k_gemm_qkv, cudaFuncAttributeMaxDynamicSharedMemorySize, GSMEM);
        cudaFuncSetAttribute(k_gemm_out, cudaFuncAttributeMaxDynamicSharedMemorySize, GSMEM);
        cudaFuncSetAttribute(k_attn, cudaFuncAttributeMaxDynamicSharedMemorySize, ATT_SMEM);
        attr_done = true;
    }

    // 5 launches; k_attn sits in the ncu capture slot (4th launch).
    k_pack_all<<<NROWS + KVROWS + 4096, 256>>>(x, gamma, beta, media, Wq, Wkv, Wout,
                                               xnp, medp, wqt, wkvt, woutt);
    k_texttime<<<BATCH, 32>>>(locs, ttb);
    k_gemm_qkv<<<768, 256, GSMEM>>>((const uint4*)xnp,  (const uint4*)wqt,  qp,
                                    (const uint4*)medp, (const uint4*)wkvt, kvp);
    k_attn<<<dim3(64, HEADS), 128, ATT_SMEM>>>(qp, kvp, ttb, aop);
    k_gemm_out<<<256, 256, GSMEM>>>((const uint4*)aop, (const uint4*)woutt, out);
}

// round 12
// speedup vs baseline: 1.0367x; 1.0367x over previous
#include <cuda_runtime.h>
#include <cuda_bf16.h>
#include <cstdint>

// ---------------------------------------------------------------------------
// MaskedCrossAttention — round 12: R10 attention structure (known best) with
//  (a) VT scatter removed: V stored K-style, PV B-frags via ldmatrix.trans
//  (b) exp2-domain online softmax (ex2.approx, log2e folded into scale)
// GEMMs / packs identical to rounds 9-11.
// bf16 hi/lo split math: D = AhBh + AhBl + AlBh (err ~1.8e-5).
// ---------------------------------------------------------------------------

#define BATCH   2
#define TTEXT   2048
#define DIM_    1024
#define TMEDIA  8
#define MTOK    256
#define HEADS   16
#define DHEAD   64
#define INNER   1024
#define NROWS   (BATCH * TTEXT)
#define KVROWS  (BATCH * TMEDIA * MTOK)
#define SCALE_  0.125f
#define SCALE2_ 0.18033688011112042f   /* 0.125 * log2(e) */
#define KDIM    1024

// ------------------------------- scratch ----------------------------------
__device__ unsigned int g_xnp   [NROWS  * KDIM];
__device__ unsigned int g_medp  [KVROWS * KDIM];
__device__ unsigned int g_aop   [NROWS  * KDIM];
__device__ unsigned int g_wqt   [INNER      * KDIM];
__device__ unsigned int g_wkvt  [2 * INNER  * KDIM];
__device__ unsigned int g_woutt [DIM_       * KDIM];
__device__ unsigned int g_qp    [NROWS  * INNER];
__device__ unsigned int g_kvp   [KVROWS * 2 * INNER];
__device__ int          g_tt[NROWS];

// --------------------------- helpers ---------------------------------------
__device__ __forceinline__ uint32_t smem_u32(const void* p) {
    uint32_t a;
    asm("{ .reg .u64 t; cvta.to.shared.u64 t, %1; cvt.u32.u64 %0, t; }" : "=r"(a) : "l"(p));
    return a;
}
#define SWZ128(o) ((o) ^ (((o) >> 3) & 0x70))

#define CP_ASYNC16(dst, src) \
    asm volatile("cp.async.cg.shared.global [%0], [%1], 16;" :: "r"(dst), "l"(src) : "memory")
#define CP_COMMIT() asm volatile("cp.async.commit_group;" ::: "memory")
#define CP_WAIT0()  asm volatile("cp.async.wait_group 0;" ::: "memory")
#define CP_WAIT1()  asm volatile("cp.async.wait_group 1;" ::: "memory")

#define LDSM4(r, addr)                                                        \
    asm volatile("ldmatrix.sync.aligned.m8n8.x4.shared.b16 {%0,%1,%2,%3}, [%4];" \
        : "=r"((r)[0]), "=r"((r)[1]), "=r"((r)[2]), "=r"((r)[3]) : "r"(addr))

#define LDSM4T(r, addr)                                                       \
    asm volatile("ldmatrix.sync.aligned.m8n8.x4.trans.shared.b16 {%0,%1,%2,%3}, [%4];" \
        : "=r"((r)[0]), "=r"((r)[1]), "=r"((r)[2]), "=r"((r)[3]) : "r"(addr))

#define MMA16816(d, a, b)                                                     \
    asm volatile("mma.sync.aligned.m16n8k16.row.col.f32.bf16.bf16.f32 "       \
        "{%0,%1,%2,%3}, {%4,%5,%6,%7}, {%8,%9}, {%0,%1,%2,%3};"               \
        : "+f"((d)[0]), "+f"((d)[1]), "+f"((d)[2]), "+f"((d)[3])              \
        : "r"((a)[0]), "r"((a)[1]), "r"((a)[2]), "r"((a)[3]),                 \
          "r"((b)[0]), "r"((b)[1]))

__device__ __forceinline__ float ex2f_(float x) {
    float y;
    asm("ex2.approx.f32 %0, %1;" : "=f"(y) : "f"(x));
    return y;
}

// ----------------------------- split helpers --------------------------------
__device__ __forceinline__ unsigned int bfpack2(float a, float b, float& ra, float& rb) {
    __nv_bfloat16 ha = __float2bfloat16(a), hb = __float2bfloat16(b);
    ra = a - __bfloat162float(ha);
    rb = b - __bfloat162float(hb);
    unsigned short xa = ((__nv_bfloat16_raw)ha).x, xb = ((__nv_bfloat16_raw)hb).x;
    return (unsigned int)xa | ((unsigned int)xb << 16);
}
__device__ __forceinline__ unsigned int bfpack2n(float a, float b) {
    __nv_bfloat16 ha = __float2bfloat16(a), hb = __float2bfloat16(b);
    unsigned short xa = ((__nv_bfloat16_raw)ha).x, xb = ((__nv_bfloat16_raw)hb).x;
    return (unsigned int)xa | ((unsigned int)xb << 16);
}
__device__ __forceinline__ void split4(float4 v, uint2& H, uint2& L) {
    float r0, r1, r2, r3;
    H.x = bfpack2(v.x, v.y, r0, r1);
    H.y = bfpack2(v.z, v.w, r2, r3);
    L.x = bfpack2n(r0, r1);
    L.y = bfpack2n(r2, r3);
}

// --------------------------- text_time cumsum -----------------------------
__global__ void k_texttime(const unsigned char* __restrict__ locs_raw,
                           int* __restrict__ tt) {
    int b = blockIdx.x;
    int lane = threadIdx.x;
    int cnt = 0;
    for (int i = lane; i < BATCH * TTEXT; i += 32) cnt += (locs_raw[i] != 0);
    #pragma unroll
    for (int off = 16; off; off >>= 1) cnt += __shfl_xor_sync(0xffffffffu, cnt, off);
    bool bytemode = (cnt >= 12);

    const int seg = TTEXT / 32;
    int base = b * TTEXT + lane * seg;
    int s = 0;
    if (bytemode) { for (int i = 0; i < seg; i++) s += (locs_raw[base + i] != 0); }
    else { const int* li = (const int*)locs_raw; for (int i = 0; i < seg; i++) s += (li[base + i] != 0); }
    int inc = s;
    #pragma unroll
    for (int off = 1; off < 32; off <<= 1) {
        int v = __shfl_up_sync(0xffffffffu, inc, off);
        if (lane >= off) inc += v;
    }
    int run = inc - s;
    int* o = tt + base;
    if (bytemode) { for (int i = 0; i < seg; i++) { run += (locs_raw[base + i] != 0); o[i] = run; } }
    else { const int* li = (const int*)locs_raw; for (int i = 0; i < seg; i++) { run += (li[base + i] != 0); o[i] = run; } }
}

// --------------------- fused pack: LN rows + media rows + weights -----------
__device__ __forceinline__ void wpack_tile(const float* __restrict__ W,
                                           unsigned int* __restrict__ out,
                                           int N, int bx, int by) {
    __shared__ float t[32][33];
    int tid = threadIdx.x;
    int k0 = by * 32, n0 = bx * 32;
    {
        int kr = tid >> 3, f4 = (tid & 7) * 4;
        float4 v = *(const float4*)&W[(size_t)(k0 + kr) * N + n0 + f4];
        t[f4 + 0][kr] = v.x; t[f4 + 1][kr] = v.y; t[f4 + 2][kr] = v.z; t[f4 + 3][kr] = v.w;
    }
    __syncthreads();
    {
        int n = tid >> 3, kq = (tid & 7) * 4;
        float4 u = make_float4(t[n][kq], t[n][kq + 1], t[n][kq + 2], t[n][kq + 3]);
        uint2 H, L;
        split4(u, H, L);
        size_t idx = (size_t)(n0 + n) * KDIM + (k0 >> 5) * 32 + (kq >> 1);
        *(uint2*)&out[idx]      = H;
        *(uint2*)&out[idx + 16] = L;
    }
}

__global__ __launch_bounds__(256) void k_pack_all(
        const float* __restrict__ x,
        const float* __restrict__ gamma,
        const float* __restrict__ beta,
        const float* __restrict__ media,
        const float* __restrict__ Wq,
        const float* __restrict__ Wkv,
        const float* __restrict__ Wout,
        unsigned int* __restrict__ xnp,
        unsigned int* __restrict__ medp,
        unsigned int* __restrict__ wqt,
        unsigned int* __restrict__ wkvt,
        unsigned int* __restrict__ woutt) {
    int bid = blockIdx.x;
    int tid = threadIdx.x;
    if (bid < NROWS) {
        int row = bid;
        const float4* xr = (const float4*)(x + (size_t)row * DIM_);
        float4 v = xr[tid];
        float s = v.x + v.y + v.z + v.w;
        float q = v.x * v.x + v.y * v.y + v.z * v.z + v.w * v.w;
        __shared__ float ss[8], sq[8];
        #pragma unroll
        for (int off = 16; off; off >>= 1) {
            s += __shfl_xor_sync(0xffffffffu, s, off);
            q += __shfl_xor_sync(0xffffffffu, q, off);
        }
        int w = tid >> 5, l = tid & 31;
        if (l == 0) { ss[w] = s; sq[w] = q; }
        __syncthreads();
        if (w == 0) {
            s = (l < 8) ? ss[l] : 0.f;
            q = (l < 8) ? sq[l] : 0.f;
            #pragma unroll
            for (int off = 4; off; off >>= 1) {
                s += __shfl_xor_sync(0xffffffffu, s, off);
                q += __shfl_xor_sync(0xffffffffu, q, off);
            }
            if (l == 0) { ss[0] = s; sq[0] = q; }
        }
        __syncthreads();
        float mu   = ss[0] * (1.0f / DIM_);
        float var  = sq[0] * (1.0f / DIM_) - mu * mu;
        float rstd = rsqrtf(var + 1e-5f);
        float4 g  = ((const float4*)gamma)[tid];
        float4 bb = ((const float4*)beta)[tid];
        float4 o;
        o.x = (v.x - mu) * rstd * g.x + bb.x;
        o.y = (v.y - mu) * rstd * g.y + bb.y;
        o.z = (v.z - mu) * rstd * g.z + bb.z;
        o.w = (v.w - mu) * rstd * g.w + bb.w;
        uint2 H, L;
        split4(o, H, L);
        size_t idx = (size_t)row * KDIM + (tid >> 3) * 32 + (tid & 7) * 2;
        *(uint2*)&xnp[idx]      = H;
        *(uint2*)&xnp[idx + 16] = L;
    } else if (bid < NROWS + KVROWS) {
        int row = bid - NROWS;
        float4 v = ((const float4*)(media + (size_t)row * KDIM))[tid];
        uint2 H, L;
        split4(v, H, L);
        size_t idx = (size_t)row * KDIM + (tid >> 3) * 32 + (tid & 7) * 2;
        *(uint2*)&medp[idx]      = H;
        *(uint2*)&medp[idx + 16] = L;
    } else {
        int wb = bid - (NROWS + KVROWS);
        if (wb < 1024) {
            wpack_tile(Wq, wqt, INNER, wb & 31, wb >> 5);
        } else if (wb < 3072) {
            int b2 = wb - 1024;
            wpack_tile(Wkv, wkvt, 2 * INNER, b2 & 63, b2 >> 6);
        } else {
            int b3 = wb - 3072;
            wpack_tile(Wout, woutt, DIM_, b3 & 31, b3 >> 5);
        }
    }
}

// --------------------- warp-MMA split-bf16 GEMM body ------------------------
#define GSTAGE_B   32768
#define GSTAGES    3
#define STAGE_ROWB 528
#define GSMEM      (GSTAGES * GSTAGE_B)

template <bool PACK>
__device__ __forceinline__ void gemm_body(const uint4* __restrict__ A,
                                          const uint4* __restrict__ B,
                                          void* __restrict__ Cout,
                                          int N, int bx, int by, char* sm) {
    const int tid = threadIdx.x, wid = tid >> 5, lane = tid & 31;
    const uint32_t smb = smem_u32(sm);
    const int rowb = by * 128, colb = bx * 128;
    const int warp_m = wid >> 2, warp_n = wid & 3;
    const int r = tid >> 3, sgi = tid & 7;
    const uint4* Ab = A + (size_t)rowb * 256;
    const uint4* Bb = B + (size_t)colb * 256;

    const int arow_l = (lane & 7) + ((lane >> 3) & 1) * 8;
    const int acol_l = (lane >> 4) * 16;
    const int brow_l = (lane & 7) + (lane >> 4) * 8;
    const int bcol_l = ((lane >> 3) & 1) * 16;

    float acc[4][4][4];
    #pragma unroll
    for (int mt = 0; mt < 4; mt++)
        #pragma unroll
        for (int nt = 0; nt < 4; nt++)
            #pragma unroll
            for (int e = 0; e < 4; e++) acc[mt][nt][e] = 0.f;

    #pragma unroll
    for (int c0 = 0; c0 < 2; c0++) {
        uint32_t stp = smb + c0 * GSTAGE_B;
        #pragma unroll
        for (int it = 0; it < 4; it++) {
            int rr = r + it * 32;
            uint32_t so = SWZ128(rr * 128 + sgi * 16);
            CP_ASYNC16(stp + so,         (const void*)(Ab + (size_t)rr * 256 + c0 * 8 + sgi));
            CP_ASYNC16(stp + 16384 + so, (const void*)(Bb + (size_t)rr * 256 + c0 * 8 + sgi));
        }
        CP_COMMIT();
    }
    CP_WAIT1();
    __syncthreads();

    for (int c = 0; c < 32; c++) {
        uint32_t stb = smb + (c % GSTAGES) * GSTAGE_B;
        if (c + 2 < 32) {
            uint32_t nstb = smb + ((c + 2) % GSTAGES) * GSTAGE_B;
            #pragma unroll
            for (int it = 0; it < 4; it++) {
                int rr = r + it * 32;
                uint32_t so = SWZ128(rr * 128 + sgi * 16);
                CP_ASYNC16(nstb + so,         (const void*)(Ab + (size_t)rr * 256 + (c + 2) * 8 + sgi));
                CP_ASYNC16(nstb + 16384 + so, (const void*)(Bb + (size_t)rr * 256 + (c + 2) * 8 + sgi));
            }
            CP_COMMIT();
        }

        #pragma unroll
        for (int s = 0; s < 2; s++) {
            const int kbh = s * 32, kbl = 64 + s * 32;
            uint32_t bh[2][4], bl[2][4];
            #pragma unroll
            for (int p = 0; p < 2; p++) {
                int bb = 16384 + (warp_n * 32 + p * 16 + brow_l) * 128 + bcol_l;
                LDSM4(bh[p], stb + SWZ128(bb + kbh));
                LDSM4(bl[p], stb + SWZ128(bb + kbl));
            }
            #pragma unroll
            for (int mt = 0; mt < 4; mt++) {
                uint32_t ah[4], al[4];
                int ab = (warp_m * 64 + mt * 16 + arow_l) * 128 + acol_l;
                LDSM4(ah, stb + SWZ128(ab + kbh));
                LDSM4(al, stb + SWZ128(ab + kbl));
                #pragma unroll
                for (int nt = 0; nt < 4; nt++) {
                    MMA16816(acc[mt][nt], ah, &bh[nt >> 1][(nt & 1) * 2]);
                    MMA16816(acc[mt][nt], ah, &bl[nt >> 1][(nt & 1) * 2]);
                    MMA16816(acc[mt][nt], al, &bh[nt >> 1][(nt & 1) * 2]);
                }
            }
        }
        if (c + 1 < 32) {
            if (c + 2 < 32) { CP_WAIT1(); } else { CP_WAIT0(); }
        }
        __syncthreads();
    }

    #pragma unroll
    for (int mt = 0; mt < 4; mt++) {
        #pragma unroll
        for (int hf = 0; hf < 2; hf++) {
            int r0 = warp_m * 64 + mt * 16 + hf * 8 + (lane >> 2);
            #pragma unroll
            for (int nt = 0; nt < 4; nt++) {
                int cl = warp_n * 32 + nt * 8 + (lane & 3) * 2;
                if (PACK) {
                    float rr0, rr1;
                    unsigned int hi = bfpack2(acc[mt][nt][hf * 2], acc[mt][nt][hf * 2 + 1], rr0, rr1);
                    unsigned int lo = bfpack2n(rr0, rr1);
                    int wl = (cl >> 5) * 32 + ((cl & 31) >> 1);
                    *(unsigned int*)(sm + r0 * STAGE_ROWB + wl * 4)      = hi;
                    *(unsigned int*)(sm + r0 * STAGE_ROWB + wl * 4 + 64) = lo;
                } else {
                    *(float2*)(sm + r0 * STAGE_ROWB + cl * 4) =
                        make_float2(acc[mt][nt][hf * 2], acc[mt][nt][hf * 2 + 1]);
                }
            }
        }
    }
    __syncthreads();
    char* Cb = (char*)Cout;
    #pragma unroll
    for (int i = 0; i < 16; i++) {
        int idx = tid + i * 256;
        int row = idx >> 5, ch = idx & 31;
        uint4 v = *(uint4*)(sm + row * STAGE_ROWB + ch * 16);
        *(uint4*)(Cb + ((size_t)(rowb + row) * N + colb + ch * 4) * 4) = v;
    }
}

__global__ __launch_bounds__(256, 2) void k_gemm_qkv(const uint4* __restrict__ Aq,
                                                     const uint4* __restrict__ Bq,
                                                     unsigned int* __restrict__ Cq,
                                                     const uint4* __restrict__ Akv,
                                                     const uint4* __restrict__ Bkv,
                                                     unsigned int* __restrict__ Ckv) {
    extern __shared__ __align__(1024) char sm[];
    int bid = blockIdx.x;
    if (bid < 256) {
        gemm_body<true>(Aq, Bq, Cq, INNER, bid & 7, bid >> 3, sm);
    } else {
        int b2 = bid - 256;
        gemm_body<true>(Akv, Bkv, Ckv, 2 * INNER, b2 & 15, b2 >> 4, sm);
    }
}

__global__ __launch_bounds__(256, 2) void k_gemm_out(const uint4* __restrict__ A,
                                                     const uint4* __restrict__ B,
                                                     float* __restrict__ C) {
    extern __shared__ __align__(1024) char sm[];
    int bid = blockIdx.x;
    gemm_body<false>(A, B, C, DIM_, bid & 7, bid >> 3, sm);
}

// ------------------------- attention (FA2-style) ----------------------------
// grid (64 q-tiles, 16 heads); block 128 (4 warps, M-split 16 rows/warp).
// Keys per chunk processed in two 128-key halves with online softmax (exp2).
// V stored K-style (direct copy); PV B-frags via ldmatrix.trans.
// SMEM: Q 2x8192 @0 | K 2x16384 @16384 | V 2x16384 @49152 | Ts @81920.
#define ATT_Q    0
#define ATT_K    16384
#define ATT_V    49152
#define ATT_TS   81920
#define ATT_SMEM (ATT_TS + 256)

__global__ __launch_bounds__(128) void k_attn(const unsigned int* __restrict__ qp,
                                              const unsigned int* __restrict__ kvp,
                                              const int* __restrict__ tt,
                                              unsigned int* __restrict__ aop) {
    extern __shared__ __align__(1024) char sm[];
    const uint32_t smb = smem_u32(sm);
    const int tid = threadIdx.x, w = tid >> 5, lane = tid & 31;
    const int tile = blockIdx.x, h = blockIdx.y;
    const int gq0 = tile * 64;
    const int b = gq0 >> 11;

    const int arow_l = (lane & 7) + ((lane >> 3) & 1) * 8;
    const int acol_l = (lane >> 4) * 16;
    const int brow_l = (lane & 7) + (lane >> 4) * 8;
    const int bcol_l = ((lane >> 3) & 1) * 16;

    int* Ts = (int*)(sm + ATT_TS);
    if (tid < 64) Ts[tid] = tt[gq0 + tid];

    // ---- load Q tile once (hi/lo panels), 8 uint4/thread
    #pragma unroll
    for (int it = 0; it < 8; it++) {
        int t = tid + it * 128;
        int row = t >> 4, rest = t & 15;
        int panel = rest >> 3, q4 = rest & 7;
        uint4 v = *(const uint4*)&qp[(size_t)(gq0 + row) * 1024 + (h * 2 + panel) * 32 + q4 * 4];
        *(uint4*)(sm + ATT_Q + panel * 8192 + SWZ128(row * 128 + q4 * 16)) = v;
    }
    __syncthreads();

    // ---- zero rows with text_time == 0 (this head's 64-word segment)
    #pragma unroll
    for (int it = 0; it < 8; it++) {
        int slot = tid + it * 128;
        int row = slot >> 4, w4 = slot & 15;
        if (Ts[row] == 0)
            *(uint4*)&aop[(size_t)(gq0 + row) * 1024 + h * 64 + w4 * 4] =
                make_uint4(0, 0, 0, 0);
    }

    int c0 = Ts[0] < 1 ? 1 : Ts[0];
    int c1 = Ts[63];
    const int rr0 = w * 16 + (lane >> 2);
    const int rr8 = rr0 + 8;

    // ldmatrix.trans lane addressing for PV B-frags
    const int t_midx = lane >> 3, t_lrow = lane & 7;
    const int t_tok_off = (t_midx & 1) * 8 + t_lrow;   // within k16 block
    const int t_seg     = (t_midx >> 1) * 16;          // byte offset for n8 pair

    for (int c = c0; c <= c1; c++) {
        float o[8][4];
        #pragma unroll
        for (int dt = 0; dt < 8; dt++)
            #pragma unroll
            for (int e = 0; e < 4; e++) o[dt][e] = 0.f;
        float pm0 = -1e30f, pm1 = -1e30f, l0 = 0.f, l1 = 0.f;

        #pragma unroll
        for (int hx = 0; hx < 2; hx++) {
            const int kbase = b * (TMEDIA * MTOK) + (c - 1) * MTOK + hx * 128;
            __syncthreads();   // K/V free of prior readers
            // ---- load K half (128 keys x 2 panels), 16 uint4/thread
            #pragma unroll
            for (int it = 0; it < 16; it++) {
                int t = tid + it * 128;
                int row = t >> 4, rest = t & 15;
                int panel = rest >> 3, q4 = rest & 7;
                uint4 v = *(const uint4*)&kvp[(size_t)(kbase + row) * 2048 + (h * 2 + panel) * 32 + q4 * 4];
                *(uint4*)(sm + ATT_K + panel * 16384 + SWZ128(row * 128 + q4 * 16)) = v;
            }
            // ---- load V half (same layout as K; dims via trans loads later)
            #pragma unroll
            for (int it = 0; it < 16; it++) {
                int t = tid + it * 128;
                int row = t >> 4, rest = t & 15;
                int panel = rest >> 3, q4 = rest & 7;
                uint4 v = *(const uint4*)&kvp[(size_t)(kbase + row) * 2048 + (32 + h * 2 + panel) * 32 + q4 * 4];
                *(uint4*)(sm + ATT_V + panel * 16384 + SWZ128(row * 128 + q4 * 16)) = v;
            }
            __syncthreads();

            // ---- QK^T: warp tile M=16, N=128, K=64 (split x3)
            float acc[16][4];
            #pragma unroll
            for (int nt = 0; nt < 16; nt++)
                #pragma unroll
                for (int e = 0; e < 4; e++) acc[nt][e] = 0.f;

            #pragma unroll
            for (int cc = 0; cc < 2; cc++) {
                uint32_t qb = smb + ATT_Q + cc * 8192;
                uint32_t kb = smb + ATT_K + cc * 16384;
                #pragma unroll
                for (int s = 0; s < 2; s++) {
                    const int kbh = s * 32, kbl = 64 + s * 32;
                    uint32_t ah[4], al[4];
                    int ab = (w * 16 + arow_l) * 128 + acol_l;
                    LDSM4(ah, qb + SWZ128(ab + kbh));
                    LDSM4(al, qb + SWZ128(ab + kbl));
                    #pragma unroll
                    for (int p4 = 0; p4 < 2; p4++) {
                        uint32_t bh[4][4], bl[4][4];
                        #pragma unroll
                        for (int p = 0; p < 4; p++) {
                            int bb = ((p4 * 4 + p) * 16 + brow_l) * 128 + bcol_l;
                            LDSM4(bh[p], kb + SWZ128(bb + kbh));
                            LDSM4(bl[p], kb + SWZ128(bb + kbl));
                        }
                        #pragma unroll
                        for (int nt = 0; nt < 8; nt++) {
                            float* d = acc[p4 * 8 + nt];
                            MMA16816(d, ah, &bh[nt >> 1][(nt & 1) * 2]);
                            MMA16816(d, ah, &bl[nt >> 1][(nt & 1) * 2]);
                            MMA16816(d, al, &bh[nt >> 1][(nt & 1) * 2]);
                        }
                    }
                }
            }

            // ---- online softmax in exp2 domain (warp-local; rows rr0, rr8)
            float m0 = -1e30f, m1 = -1e30f;
            #pragma unroll
            for (int nt = 0; nt < 16; nt++) {
                acc[nt][0] *= SCALE2_; acc[nt][1] *= SCALE2_;
                acc[nt][2] *= SCALE2_; acc[nt][3] *= SCALE2_;
                m0 = fmaxf(m0, fmaxf(acc[nt][0], acc[nt][1]));
                m1 = fmaxf(m1, fmaxf(acc[nt][2], acc[nt][3]));
            }
            m0 = fmaxf(m0, __shfl_xor_sync(0xffffffffu, m0, 1));
            m0 = fmaxf(m0, __shfl_xor_sync(0xffffffffu, m0, 2));
            m1 = fmaxf(m1, __shfl_xor_sync(0xffffffffu, m1, 1));
            m1 = fmaxf(m1, __shfl_xor_sync(0xffffffffu, m1, 2));
            float n0 = fmaxf(pm0, m0), n1 = fmaxf(pm1, m1);
            float a0 = ex2f_(pm0 - n0), a1 = ex2f_(pm1 - n1);
            #pragma unroll
            for (int dt = 0; dt < 8; dt++) {
                o[dt][0] *= a0; o[dt][1] *= a0;
                o[dt][2] *= a1; o[dt][3] *= a1;
            }
            float s0 = 0.f, s1 = 0.f;
            #pragma unroll
            for (int nt = 0; nt < 16; nt++) {
                float e0 = ex2f_(acc[nt][0] - n0), e1 = ex2f_(acc[nt][1] - n0);
                float e2 = ex2f_(acc[nt][2] - n1), e3 = ex2f_(acc[nt][3] - n1);
                acc[nt][0] = e0; acc[nt][1] = e1; acc[nt][2] = e2; acc[nt][3] = e3;
                s0 += e0 + e1; s1 += e2 + e3;
            }
            s0 += __shfl_xor_sync(0xffffffffu, s0, 1);
            s0 += __shfl_xor_sync(0xffffffffu, s0, 2);
            s1 += __shfl_xor_sync(0xffffffffu, s1, 1);
            s1 += __shfl_xor_sync(0xffffffffu, s1, 2);
            l0 = l0 * a0 + s0; l1 = l1 * a1 + s1;
            pm0 = n0; pm1 = n1;

            // ---- PV: P from registers; V B-frags via ldmatrix.trans
            #pragma unroll
            for (int ks = 0; ks < 8; ks++) {
                uint32_t aph[4], apl[4];
                float q0, q1;
                aph[0] = bfpack2(acc[2 * ks][0],     acc[2 * ks][1],     q0, q1);
                apl[0] = bfpack2n(q0, q1);
                aph[1] = bfpack2(acc[2 * ks][2],     acc[2 * ks][3],     q0, q1);
                apl[1] = bfpack2n(q0, q1);
                aph[2] = bfpack2(acc[2 * ks + 1][0], acc[2 * ks + 1][1], q0, q1);
                apl[2] = bfpack2n(q0, q1);
                aph[3] = bfpack2(acc[2 * ks + 1][2], acc[2 * ks + 1][3], q0, q1);
                apl[3] = bfpack2n(q0, q1);

                int token = ks * 16 + t_tok_off;
                #pragma unroll
                for (int d16 = 0; d16 < 4; d16++) {
                    uint32_t vb = smb + ATT_V + (d16 >> 1) * 16384;
                    int boff = (d16 & 1) * 32 + t_seg;
                    uint32_t bvh4[4], bvl4[4];
                    LDSM4T(bvh4, vb + SWZ128(token * 128 + boff));
                    LDSM4T(bvl4, vb + SWZ128(token * 128 + 64 + boff));
                    #pragma unroll
                    for (int dt2 = 0; dt2 < 2; dt2++) {
                        int dt = d16 * 2 + dt2;
                        MMA16816(o[dt], aph, &bvh4[dt2 * 2]);
                        MMA16816(o[dt], aph, &bvl4[dt2 * 2]);
                        MMA16816(o[dt], apl, &bvh4[dt2 * 2]);
                    }
                }
            }
        }

        // ---- store rows belonging to this chunk (deferred normalization)
        float inv0 = 1.0f / l0, inv1 = 1.0f / l1;
        bool st0 = (Ts[rr0] == c), st1 = (Ts[rr8] == c);
        if (st0 || st1) {
            #pragma unroll
            for (int dt = 0; dt < 8; dt++) {
                int d2 = dt * 8 + (lane & 3) * 2;
                int wofs = (h * 2 + (d2 >> 5)) * 32 + ((d2 & 31) >> 1);
                if (st0) {
                    float q0, q1;
                    unsigned int hi = bfpack2(o[dt][0] * inv0, o[dt][1] * inv0, q0, q1);
                    unsigned int lo = bfpack2n(q0, q1);
                    size_t idx = (size_t)(gq0 + rr0) * 1024 + wofs;
                    aop[idx] = hi; aop[idx + 16] = lo;
                }
                if (st1) {
                    float q0, q1;
                    unsigned int hi = bfpack2(o[dt][2] * inv1, o[dt][3] * inv1, q0, q1);
                    unsigned int lo = bfpack2n(q0, q1);
                    size_t idx = (size_t)(gq0 + rr8) * 1024 + wofs;
                    aop[idx] = hi; aop[idx + 16] = lo;
                }
            }
        }
    }
}

// ------------------------------- launcher ---------------------------------
extern "C" void kernel_launch(void* const* d_in, const int* in_sizes, int n_in,
                              void* d_out, int out_size) {
    const float*         x     = (const float*)d_in[0];
    const float*         media = (const float*)d_in[1];
    const unsigned char* locs  = (const unsigned char*)d_in[2];
    const float*         gamma = (const float*)d_in[3];
    const float*         beta  = (const float*)d_in[4];
    const float*         Wq    = (const float*)d_in[5];
    const float*         Wkv   = (const float*)d_in[6];
    const float*         Wout  = (const float*)d_in[7];
    float*               out   = (float*)d_out;

    unsigned int *xnp, *medp, *aop, *wqt, *wkvt, *woutt, *qp, *kvp;
    int *ttb;
    cudaGetSymbolAddress((void**)&xnp,   g_xnp);
    cudaGetSymbolAddress((void**)&medp,  g_medp);
    cudaGetSymbolAddress((void**)&aop,   g_aop);
    cudaGetSymbolAddress((void**)&wqt,   g_wqt);
    cudaGetSymbolAddress((void**)&wkvt,  g_wkvt);
    cudaGetSymbolAddress((void**)&woutt, g_woutt);
    cudaGetSymbolAddress((void**)&qp,    g_qp);
    cudaGetSymbolAddress((void**)&kvp,   g_kvp);
    cudaGetSymbolAddress((void**)&ttb,   g_tt);

    static bool attr_done = false;
    if (!attr_done) {
        cudaFuncSetAttribute(k_gemm_qkv, cudaFuncAttributeMaxDynamicSharedMemorySize, GSMEM);
        cudaFuncSetAttribute(k_gemm_out, cudaFuncAttributeMaxDynamicSharedMemorySize, GSMEM);
        cudaFuncSetAttribute(k_attn, cudaFuncAttributeMaxDynamicSharedMemorySize, ATT_SMEM);
        attr_done = true;
    }

    // 5 launches; k_attn sits in the ncu capture slot (4th launch).
    k_pack_all<<<NROWS + KVROWS + 4096, 256>>>(x, gamma, beta, media, Wq, Wkv, Wout,
                                               xnp, medp, wqt, wkvt, woutt);
    k_texttime<<<BATCH, 32>>>(locs, ttb);
    k_gemm_qkv<<<768, 256, GSMEM>>>((const uint4*)xnp,  (const uint4*)wqt,  qp,
                                    (const uint4*)medp, (const uint4*)wkvt, kvp);
    k_attn<<<dim3(64, HEADS), 128, ATT_SMEM>>>(qp, kvp, ttb, aop);
    k_gemm_out<<<256, 256, GSMEM>>>((const uint4*)aop, (const uint4*)woutt, out);
}

// round 13
// speedup vs baseline: 1.0748x; 1.0368x over previous
#include <cuda_runtime.h>
#include <cuda_bf16.h>
#include <cstdint>

// ---------------------------------------------------------------------------
// MaskedCrossAttention — round 13: Q-in-registers attention, 3 CTAs/SM.
//  * Q fragments loaded directly from packed global (bf16 pairs == frag words)
//  * K/V filled via cp.async; smem 64.5KB -> launch_bounds(128,3)
//  * trans-V PV + exp2 softmax from round 12 (validated)
// GEMMs / packs identical to rounds 9-12.
// bf16 hi/lo split math: D = AhBh + AhBl + AlBh (err ~1.8e-5).
// ---------------------------------------------------------------------------

#define BATCH   2
#define TTEXT   2048
#define DIM_    1024
#define TMEDIA  8
#define MTOK    256
#define HEADS   16
#define DHEAD   64
#define INNER   1024
#define NROWS   (BATCH * TTEXT)
#define KVROWS  (BATCH * TMEDIA * MTOK)
#define SCALE_  0.125f
#define SCALE2_ 0.18033688011112042f   /* 0.125 * log2(e) */
#define KDIM    1024

// ------------------------------- scratch ----------------------------------
__device__ unsigned int g_xnp   [NROWS  * KDIM];
__device__ unsigned int g_medp  [KVROWS * KDIM];
__device__ unsigned int g_aop   [NROWS  * KDIM];
__device__ unsigned int g_wqt   [INNER      * KDIM];
__device__ unsigned int g_wkvt  [2 * INNER  * KDIM];
__device__ unsigned int g_woutt [DIM_       * KDIM];
__device__ unsigned int g_qp    [NROWS  * INNER];
__device__ unsigned int g_kvp   [KVROWS * 2 * INNER];
__device__ int          g_tt[NROWS];

// --------------------------- helpers ---------------------------------------
__device__ __forceinline__ uint32_t smem_u32(const void* p) {
    uint32_t a;
    asm("{ .reg .u64 t; cvta.to.shared.u64 t, %1; cvt.u32.u64 %0, t; }" : "=r"(a) : "l"(p));
    return a;
}
#define SWZ128(o) ((o) ^ (((o) >> 3) & 0x70))

#define CP_ASYNC16(dst, src) \
    asm volatile("cp.async.cg.shared.global [%0], [%1], 16;" :: "r"(dst), "l"(src) : "memory")
#define CP_COMMIT() asm volatile("cp.async.commit_group;" ::: "memory")
#define CP_WAIT0()  asm volatile("cp.async.wait_group 0;" ::: "memory")
#define CP_WAIT1()  asm volatile("cp.async.wait_group 1;" ::: "memory")

#define LDSM4(r, addr)                                                        \
    asm volatile("ldmatrix.sync.aligned.m8n8.x4.shared.b16 {%0,%1,%2,%3}, [%4];" \
        : "=r"((r)[0]), "=r"((r)[1]), "=r"((r)[2]), "=r"((r)[3]) : "r"(addr))

#define LDSM4T(r, addr)                                                       \
    asm volatile("ldmatrix.sync.aligned.m8n8.x4.trans.shared.b16 {%0,%1,%2,%3}, [%4];" \
        : "=r"((r)[0]), "=r"((r)[1]), "=r"((r)[2]), "=r"((r)[3]) : "r"(addr))

#define MMA16816(d, a, b)                                                     \
    asm volatile("mma.sync.aligned.m16n8k16.row.col.f32.bf16.bf16.f32 "       \
        "{%0,%1,%2,%3}, {%4,%5,%6,%7}, {%8,%9}, {%0,%1,%2,%3};"               \
        : "+f"((d)[0]), "+f"((d)[1]), "+f"((d)[2]), "+f"((d)[3])              \
        : "r"((a)[0]), "r"((a)[1]), "r"((a)[2]), "r"((a)[3]),                 \
          "r"((b)[0]), "r"((b)[1]))

__device__ __forceinline__ float ex2f_(float x) {
    float y;
    asm("ex2.approx.f32 %0, %1;" : "=f"(y) : "f"(x));
    return y;
}

// ----------------------------- split helpers --------------------------------
__device__ __forceinline__ unsigned int bfpack2(float a, float b, float& ra, float& rb) {
    __nv_bfloat16 ha = __float2bfloat16(a), hb = __float2bfloat16(b);
    ra = a - __bfloat162float(ha);
    rb = b - __bfloat162float(hb);
    unsigned short xa = ((__nv_bfloat16_raw)ha).x, xb = ((__nv_bfloat16_raw)hb).x;
    return (unsigned int)xa | ((unsigned int)xb << 16);
}
__device__ __forceinline__ unsigned int bfpack2n(float a, float b) {
    __nv_bfloat16 ha = __float2bfloat16(a), hb = __float2bfloat16(b);
    unsigned short xa = ((__nv_bfloat16_raw)ha).x, xb = ((__nv_bfloat16_raw)hb).x;
    return (unsigned int)xa | ((unsigned int)xb << 16);
}
__device__ __forceinline__ void split4(float4 v, uint2& H, uint2& L) {
    float r0, r1, r2, r3;
    H.x = bfpack2(v.x, v.y, r0, r1);
    H.y = bfpack2(v.z, v.w, r2, r3);
    L.x = bfpack2n(r0, r1);
    L.y = bfpack2n(r2, r3);
}

// --------------------------- text_time cumsum -----------------------------
__global__ void k_texttime(const unsigned char* __restrict__ locs_raw,
                           int* __restrict__ tt) {
    int b = blockIdx.x;
    int lane = threadIdx.x;
    int cnt = 0;
    for (int i = lane; i < BATCH * TTEXT; i += 32) cnt += (locs_raw[i] != 0);
    #pragma unroll
    for (int off = 16; off; off >>= 1) cnt += __shfl_xor_sync(0xffffffffu, cnt, off);
    bool bytemode = (cnt >= 12);

    const int seg = TTEXT / 32;
    int base = b * TTEXT + lane * seg;
    int s = 0;
    if (bytemode) { for (int i = 0; i < seg; i++) s += (locs_raw[base + i] != 0); }
    else { const int* li = (const int*)locs_raw; for (int i = 0; i < seg; i++) s += (li[base + i] != 0); }
    int inc = s;
    #pragma unroll
    for (int off = 1; off < 32; off <<= 1) {
        int v = __shfl_up_sync(0xffffffffu, inc, off);
        if (lane >= off) inc += v;
    }
    int run = inc - s;
    int* o = tt + base;
    if (bytemode) { for (int i = 0; i < seg; i++) { run += (locs_raw[base + i] != 0); o[i] = run; } }
    else { const int* li = (const int*)locs_raw; for (int i = 0; i < seg; i++) { run += (li[base + i] != 0); o[i] = run; } }
}

// --------------------- fused pack: LN rows + media rows + weights -----------
__device__ __forceinline__ void wpack_tile(const float* __restrict__ W,
                                           unsigned int* __restrict__ out,
                                           int N, int bx, int by) {
    __shared__ float t[32][33];
    int tid = threadIdx.x;
    int k0 = by * 32, n0 = bx * 32;
    {
        int kr = tid >> 3, f4 = (tid & 7) * 4;
        float4 v = *(const float4*)&W[(size_t)(k0 + kr) * N + n0 + f4];
        t[f4 + 0][kr] = v.x; t[f4 + 1][kr] = v.y; t[f4 + 2][kr] = v.z; t[f4 + 3][kr] = v.w;
    }
    __syncthreads();
    {
        int n = tid >> 3, kq = (tid & 7) * 4;
        float4 u = make_float4(t[n][kq], t[n][kq + 1], t[n][kq + 2], t[n][kq + 3]);
        uint2 H, L;
        split4(u, H, L);
        size_t idx = (size_t)(n0 + n) * KDIM + (k0 >> 5) * 32 + (kq >> 1);
        *(uint2*)&out[idx]      = H;
        *(uint2*)&out[idx + 16] = L;
    }
}

__global__ __launch_bounds__(256) void k_pack_all(
        const float* __restrict__ x,
        const float* __restrict__ gamma,
        const float* __restrict__ beta,
        const float* __restrict__ media,
        const float* __restrict__ Wq,
        const float* __restrict__ Wkv,
        const float* __restrict__ Wout,
        unsigned int* __restrict__ xnp,
        unsigned int* __restrict__ medp,
        unsigned int* __restrict__ wqt,
        unsigned int* __restrict__ wkvt,
        unsigned int* __restrict__ woutt) {
    int bid = blockIdx.x;
    int tid = threadIdx.x;
    if (bid < NROWS) {
        int row = bid;
        const float4* xr = (const float4*)(x + (size_t)row * DIM_);
        float4 v = xr[tid];
        float s = v.x + v.y + v.z + v.w;
        float q = v.x * v.x + v.y * v.y + v.z * v.z + v.w * v.w;
        __shared__ float ss[8], sq[8];
        #pragma unroll
        for (int off = 16; off; off >>= 1) {
            s += __shfl_xor_sync(0xffffffffu, s, off);
            q += __shfl_xor_sync(0xffffffffu, q, off);
        }
        int w = tid >> 5, l = tid & 31;
        if (l == 0) { ss[w] = s; sq[w] = q; }
        __syncthreads();
        if (w == 0) {
            s = (l < 8) ? ss[l] : 0.f;
            q = (l < 8) ? sq[l] : 0.f;
            #pragma unroll
            for (int off = 4; off; off >>= 1) {
                s += __shfl_xor_sync(0xffffffffu, s, off);
                q += __shfl_xor_sync(0xffffffffu, q, off);
            }
            if (l == 0) { ss[0] = s; sq[0] = q; }
        }
        __syncthreads();
        float mu   = ss[0] * (1.0f / DIM_);
        float var  = sq[0] * (1.0f / DIM_) - mu * mu;
        float rstd = rsqrtf(var + 1e-5f);
        float4 g  = ((const float4*)gamma)[tid];
        float4 bb = ((const float4*)beta)[tid];
        float4 o;
        o.x = (v.x - mu) * rstd * g.x + bb.x;
        o.y = (v.y - mu) * rstd * g.y + bb.y;
        o.z = (v.z - mu) * rstd * g.z + bb.z;
        o.w = (v.w - mu) * rstd * g.w + bb.w;
        uint2 H, L;
        split4(o, H, L);
        size_t idx = (size_t)row * KDIM + (tid >> 3) * 32 + (tid & 7) * 2;
        *(uint2*)&xnp[idx]      = H;
        *(uint2*)&xnp[idx + 16] = L;
    } else if (bid < NROWS + KVROWS) {
        int row = bid - NROWS;
        float4 v = ((const float4*)(media + (size_t)row * KDIM))[tid];
        uint2 H, L;
        split4(v, H, L);
        size_t idx = (size_t)row * KDIM + (tid >> 3) * 32 + (tid & 7) * 2;
        *(uint2*)&medp[idx]      = H;
        *(uint2*)&medp[idx + 16] = L;
    } else {
        int wb = bid - (NROWS + KVROWS);
        if (wb < 1024) {
            wpack_tile(Wq, wqt, INNER, wb & 31, wb >> 5);
        } else if (wb < 3072) {
            int b2 = wb - 1024;
            wpack_tile(Wkv, wkvt, 2 * INNER, b2 & 63, b2 >> 6);
        } else {
            int b3 = wb - 3072;
            wpack_tile(Wout, woutt, DIM_, b3 & 31, b3 >> 5);
        }
    }
}

// --------------------- warp-MMA split-bf16 GEMM body ------------------------
#define GSTAGE_B   32768
#define GSTAGES    3
#define STAGE_ROWB 528
#define GSMEM      (GSTAGES * GSTAGE_B)

template <bool PACK>
__device__ __forceinline__ void gemm_body(const uint4* __restrict__ A,
                                          const uint4* __restrict__ B,
                                          void* __restrict__ Cout,
                                          int N, int bx, int by, char* sm) {
    const int tid = threadIdx.x, wid = tid >> 5, lane = tid & 31;
    const uint32_t smb = smem_u32(sm);
    const int rowb = by * 128, colb = bx * 128;
    const int warp_m = wid >> 2, warp_n = wid & 3;
    const int r = tid >> 3, sgi = tid & 7;
    const uint4* Ab = A + (size_t)rowb * 256;
    const uint4* Bb = B + (size_t)colb * 256;

    const int arow_l = (lane & 7) + ((lane >> 3) & 1) * 8;
    const int acol_l = (lane >> 4) * 16;
    const int brow_l = (lane & 7) + (lane >> 4) * 8;
    const int bcol_l = ((lane >> 3) & 1) * 16;

    float acc[4][4][4];
    #pragma unroll
    for (int mt = 0; mt < 4; mt++)
        #pragma unroll
        for (int nt = 0; nt < 4; nt++)
            #pragma unroll
            for (int e = 0; e < 4; e++) acc[mt][nt][e] = 0.f;

    #pragma unroll
    for (int c0 = 0; c0 < 2; c0++) {
        uint32_t stp = smb + c0 * GSTAGE_B;
        #pragma unroll
        for (int it = 0; it < 4; it++) {
            int rr = r + it * 32;
            uint32_t so = SWZ128(rr * 128 + sgi * 16);
            CP_ASYNC16(stp + so,         (const void*)(Ab + (size_t)rr * 256 + c0 * 8 + sgi));
            CP_ASYNC16(stp + 16384 + so, (const void*)(Bb + (size_t)rr * 256 + c0 * 8 + sgi));
        }
        CP_COMMIT();
    }
    CP_WAIT1();
    __syncthreads();

    for (int c = 0; c < 32; c++) {
        uint32_t stb = smb + (c % GSTAGES) * GSTAGE_B;
        if (c + 2 < 32) {
            uint32_t nstb = smb + ((c + 2) % GSTAGES) * GSTAGE_B;
            #pragma unroll
            for (int it = 0; it < 4; it++) {
                int rr = r + it * 32;
                uint32_t so = SWZ128(rr * 128 + sgi * 16);
                CP_ASYNC16(nstb + so,         (const void*)(Ab + (size_t)rr * 256 + (c + 2) * 8 + sgi));
                CP_ASYNC16(nstb + 16384 + so, (const void*)(Bb + (size_t)rr * 256 + (c + 2) * 8 + sgi));
            }
            CP_COMMIT();
        }

        #pragma unroll
        for (int s = 0; s < 2; s++) {
            const int kbh = s * 32, kbl = 64 + s * 32;
            uint32_t bh[2][4], bl[2][4];
            #pragma unroll
            for (int p = 0; p < 2; p++) {
                int bb = 16384 + (warp_n * 32 + p * 16 + brow_l) * 128 + bcol_l;
                LDSM4(bh[p], stb + SWZ128(bb + kbh));
                LDSM4(bl[p], stb + SWZ128(bb + kbl));
            }
            #pragma unroll
            for (int mt = 0; mt < 4; mt++) {
                uint32_t ah[4], al[4];
                int ab = (warp_m * 64 + mt * 16 + arow_l) * 128 + acol_l;
                LDSM4(ah, stb + SWZ128(ab + kbh));
                LDSM4(al, stb + SWZ128(ab + kbl));
                #pragma unroll
                for (int nt = 0; nt < 4; nt++) {
                    MMA16816(acc[mt][nt], ah, &bh[nt >> 1][(nt & 1) * 2]);
                    MMA16816(acc[mt][nt], ah, &bl[nt >> 1][(nt & 1) * 2]);
                    MMA16816(acc[mt][nt], al, &bh[nt >> 1][(nt & 1) * 2]);
                }
            }
        }
        if (c + 1 < 32) {
            if (c + 2 < 32) { CP_WAIT1(); } else { CP_WAIT0(); }
        }
        __syncthreads();
    }

    #pragma unroll
    for (int mt = 0; mt < 4; mt++) {
        #pragma unroll
        for (int hf = 0; hf < 2; hf++) {
            int r0 = warp_m * 64 + mt * 16 + hf * 8 + (lane >> 2);
            #pragma unroll
            for (int nt = 0; nt < 4; nt++) {
                int cl = warp_n * 32 + nt * 8 + (lane & 3) * 2;
                if (PACK) {
                    float rr0, rr1;
                    unsigned int hi = bfpack2(acc[mt][nt][hf * 2], acc[mt][nt][hf * 2 + 1], rr0, rr1);
                    unsigned int lo = bfpack2n(rr0, rr1);
                    int wl = (cl >> 5) * 32 + ((cl & 31) >> 1);
                    *(unsigned int*)(sm + r0 * STAGE_ROWB + wl * 4)      = hi;
                    *(unsigned int*)(sm + r0 * STAGE_ROWB + wl * 4 + 64) = lo;
                } else {
                    *(float2*)(sm + r0 * STAGE_ROWB + cl * 4) =
                        make_float2(acc[mt][nt][hf * 2], acc[mt][nt][hf * 2 + 1]);
                }
            }
        }
    }
    __syncthreads();
    char* Cb = (char*)Cout;
    #pragma unroll
    for (int i = 0; i < 16; i++) {
        int idx = tid + i * 256;
        int row = idx >> 5, ch = idx & 31;
        uint4 v = *(uint4*)(sm + row * STAGE_ROWB + ch * 16);
        *(uint4*)(Cb + ((size_t)(rowb + row) * N + colb + ch * 4) * 4) = v;
    }
}

__global__ __launch_bounds__(256, 2) void k_gemm_qkv(const uint4* __restrict__ Aq,
                                                     const uint4* __restrict__ Bq,
                                                     unsigned int* __restrict__ Cq,
                                                     const uint4* __restrict__ Akv,
                                                     const uint4* __restrict__ Bkv,
                                                     unsigned int* __restrict__ Ckv) {
    extern __shared__ __align__(1024) char sm[];
    int bid = blockIdx.x;
    if (bid < 256) {
        gemm_body<true>(Aq, Bq, Cq, INNER, bid & 7, bid >> 3, sm);
    } else {
        int b2 = bid - 256;
        gemm_body<true>(Akv, Bkv, Ckv, 2 * INNER, b2 & 15, b2 >> 4, sm);
    }
}

__global__ __launch_bounds__(256, 2) void k_gemm_out(const uint4* __restrict__ A,
                                                     const uint4* __restrict__ B,
                                                     float* __restrict__ C) {
    extern __shared__ __align__(1024) char sm[];
    int bid = blockIdx.x;
    gemm_body<false>(A, B, C, DIM_, bid & 7, bid >> 3, sm);
}

// ------------------- attention (Q-in-registers, 3 CTAs/SM) ------------------
// grid (64 q-tiles, 16 heads); block 128 (4 warps, M-split 16 rows/warp).
// Q fragments live in registers (loaded directly from packed global).
// Keys per chunk processed in two 128-key halves; exp2 online softmax;
// V stored K-style, PV B-frags via ldmatrix.trans.
// SMEM: K 2x16384 @0 | V 2x16384 @32768 | Ts @65536.
#define ATT_K    0
#define ATT_V    32768
#define ATT_TS   65536
#define ATT_SMEM (ATT_TS + 256)

__global__ __launch_bounds__(128, 3) void k_attn(const unsigned int* __restrict__ qp,
                                                 const unsigned int* __restrict__ kvp,
                                                 const int* __restrict__ tt,
                                                 unsigned int* __restrict__ aop) {
    extern __shared__ __align__(1024) char sm[];
    const uint32_t smb = smem_u32(sm);
    const int tid = threadIdx.x, w = tid >> 5, lane = tid & 31;
    const int tile = blockIdx.x, h = blockIdx.y;
    const int gq0 = tile * 64;
    const int b = gq0 >> 11;

    const int brow_l = (lane & 7) + (lane >> 4) * 8;
    const int bcol_l = ((lane >> 3) & 1) * 16;

    int* Ts = (int*)(sm + ATT_TS);
    if (tid < 64) Ts[tid] = tt[gq0 + tid];

    const int rr0 = w * 16 + (lane >> 2);
    const int rr8 = rr0 + 8;

    // ---- Q fragments direct from packed global: qh/ql[kstep][a0..a3]
    uint32_t qh[4][4], ql[4][4];
    {
        const unsigned int* q0p = qp + (size_t)(gq0 + rr0) * 1024 + h * 64;
        const unsigned int* q8p = qp + (size_t)(gq0 + rr8) * 1024 + h * 64;
        #pragma unroll
        for (int ks = 0; ks < 4; ks++) {
            int off = (ks >> 1) * 32 + (ks & 1) * 8 + (lane & 3);
            qh[ks][0] = q0p[off];      qh[ks][1] = q8p[off];
            qh[ks][2] = q0p[off + 4];  qh[ks][3] = q8p[off + 4];
            ql[ks][0] = q0p[off + 16]; ql[ks][1] = q8p[off + 16];
            ql[ks][2] = q0p[off + 20]; ql[ks][3] = q8p[off + 20];
        }
    }
    __syncthreads();   // Ts visible

    // ---- zero rows with text_time == 0 (this head's 64-word segment)
    #pragma unroll
    for (int it = 0; it < 8; it++) {
        int slot = tid + it * 128;
        int row = slot >> 4, w4 = slot & 15;
        if (Ts[row] == 0)
            *(uint4*)&aop[(size_t)(gq0 + row) * 1024 + h * 64 + w4 * 4] =
                make_uint4(0, 0, 0, 0);
    }

    int c0 = Ts[0] < 1 ? 1 : Ts[0];
    int c1 = Ts[63];

    // ldmatrix.trans lane addressing for PV B-frags
    const int t_midx = lane >> 3, t_lrow = lane & 7;
    const int t_tok_off = (t_midx & 1) * 8 + t_lrow;
    const int t_seg     = (t_midx >> 1) * 16;

    for (int c = c0; c <= c1; c++) {
        float o[8][4];
        #pragma unroll
        for (int dt = 0; dt < 8; dt++)
            #pragma unroll
            for (int e = 0; e < 4; e++) o[dt][e] = 0.f;
        float pm0 = -1e30f, pm1 = -1e30f, l0 = 0.f, l1 = 0.f;

        #pragma unroll
        for (int hx = 0; hx < 2; hx++) {
            const int kbase = b * (TMEDIA * MTOK) + (c - 1) * MTOK + hx * 128;
            __syncthreads();   // K/V free of prior readers
            // ---- cp.async fill: K half then V half (16 + 16 x 16B / thread)
            #pragma unroll
            for (int it = 0; it < 16; it++) {
                int t = tid + it * 128;
                int row = t >> 4, rest = t & 15;
                int panel = rest >> 3, q4 = rest & 7;
                uint32_t so = SWZ128(row * 128 + q4 * 16);
                CP_ASYNC16(smb + ATT_K + panel * 16384 + so,
                           (const void*)&kvp[(size_t)(kbase + row) * 2048 + (h * 2 + panel) * 32 + q4 * 4]);
                CP_ASYNC16(smb + ATT_V + panel * 16384 + so,
                           (const void*)&kvp[(size_t)(kbase + row) * 2048 + (32 + h * 2 + panel) * 32 + q4 * 4]);
            }
            CP_COMMIT();
            CP_WAIT0();
            __syncthreads();

            // ---- QK^T: warp tile M=16, N=128, K=64 (split x3), Q from regs
            float acc[16][4];
            #pragma unroll
            for (int nt = 0; nt < 16; nt++)
                #pragma unroll
                for (int e = 0; e < 4; e++) acc[nt][e] = 0.f;

            #pragma unroll
            for (int cc = 0; cc < 2; cc++) {
                uint32_t kb = smb + ATT_K + cc * 16384;
                #pragma unroll
                for (int s = 0; s < 2; s++) {
                    const int kstep = cc * 2 + s;
                    const int kbh = s * 32, kbl = 64 + s * 32;
                    #pragma unroll
                    for (int p4 = 0; p4 < 2; p4++) {
                        uint32_t bh[4][4], bl[4][4];
                        #pragma unroll
                        for (int p = 0; p < 4; p++) {
                            int bb = ((p4 * 4 + p) * 16 + brow_l) * 128 + bcol_l;
                            LDSM4(bh[p], kb + SWZ128(bb + kbh));
                            LDSM4(bl[p], kb + SWZ128(bb + kbl));
                        }
                        #pragma unroll
                        for (int nt = 0; nt < 8; nt++) {
                            float* d = acc[p4 * 8 + nt];
                            MMA16816(d, qh[kstep], &bh[nt >> 1][(nt & 1) * 2]);
                            MMA16816(d, qh[kstep], &bl[nt >> 1][(nt & 1) * 2]);
                            MMA16816(d, ql[kstep], &bh[nt >> 1][(nt & 1) * 2]);
                        }
                    }
                }
            }

            // ---- online softmax in exp2 domain (warp-local; rows rr0, rr8)
            float m0 = -1e30f, m1 = -1e30f;
            #pragma unroll
            for (int nt = 0; nt < 16; nt++) {
                acc[nt][0] *= SCALE2_; acc[nt][1] *= SCALE2_;
                acc[nt][2] *= SCALE2_; acc[nt][3] *= SCALE2_;
                m0 = fmaxf(m0, fmaxf(acc[nt][0], acc[nt][1]));
                m1 = fmaxf(m1, fmaxf(acc[nt][2], acc[nt][3]));
            }
            m0 = fmaxf(m0, __shfl_xor_sync(0xffffffffu, m0, 1));
            m0 = fmaxf(m0, __shfl_xor_sync(0xffffffffu, m0, 2));
            m1 = fmaxf(m1, __shfl_xor_sync(0xffffffffu, m1, 1));
            m1 = fmaxf(m1, __shfl_xor_sync(0xffffffffu, m1, 2));
            float n0 = fmaxf(pm0, m0), n1 = fmaxf(pm1, m1);
            float a0 = ex2f_(pm0 - n0), a1 = ex2f_(pm1 - n1);
            #pragma unroll
            for (int dt = 0; dt < 8; dt++) {
                o[dt][0] *= a0; o[dt][1] *= a0;
                o[dt][2] *= a1; o[dt][3] *= a1;
            }
            float s0 = 0.f, s1 = 0.f;
            #pragma unroll
            for (int nt = 0; nt < 16; nt++) {
                float e0 = ex2f_(acc[nt][0] - n0), e1 = ex2f_(acc[nt][1] - n0);
                float e2 = ex2f_(acc[nt][2] - n1), e3 = ex2f_(acc[nt][3] - n1);
                acc[nt][0] = e0; acc[nt][1] = e1; acc[nt][2] = e2; acc[nt][3] = e3;
                s0 += e0 + e1; s1 += e2 + e3;
            }
            s0 += __shfl_xor_sync(0xffffffffu, s0, 1);
            s0 += __shfl_xor_sync(0xffffffffu, s0, 2);
            s1 += __shfl_xor_sync(0xffffffffu, s1, 1);
            s1 += __shfl_xor_sync(0xffffffffu, s1, 2);
            l0 = l0 * a0 + s0; l1 = l1 * a1 + s1;
            pm0 = n0; pm1 = n1;

            // ---- PV: P from registers; V B-frags via ldmatrix.trans
            #pragma unroll
            for (int ks = 0; ks < 8; ks++) {
                uint32_t aph[4], apl[4];
                float q0, q1;
                aph[0] = bfpack2(acc[2 * ks][0],     acc[2 * ks][1],     q0, q1);
                apl[0] = bfpack2n(q0, q1);
                aph[1] = bfpack2(acc[2 * ks][2],     acc[2 * ks][3],     q0, q1);
                apl[1] = bfpack2n(q0, q1);
                aph[2] = bfpack2(acc[2 * ks + 1][0], acc[2 * ks + 1][1], q0, q1);
                apl[2] = bfpack2n(q0, q1);
                aph[3] = bfpack2(acc[2 * ks + 1][2], acc[2 * ks + 1][3], q0, q1);
                apl[3] = bfpack2n(q0, q1);

                int token = ks * 16 + t_tok_off;
                #pragma unroll
                for (int d16 = 0; d16 < 4; d16++) {
                    uint32_t vb = smb + ATT_V + (d16 >> 1) * 16384;
                    int boff = (d16 & 1) * 32 + t_seg;
                    uint32_t bvh4[4], bvl4[4];
                    LDSM4T(bvh4, vb + SWZ128(token * 128 + boff));
                    LDSM4T(bvl4, vb + SWZ128(token * 128 + 64 + boff));
                    #pragma unroll
                    for (int dt2 = 0; dt2 < 2; dt2++) {
                        int dt = d16 * 2 + dt2;
                        MMA16816(o[dt], aph, &bvh4[dt2 * 2]);
                        MMA16816(o[dt], aph, &bvl4[dt2 * 2]);
                        MMA16816(o[dt], apl, &bvh4[dt2 * 2]);
                    }
                }
            }
        }

        // ---- store rows belonging to this chunk (deferred normalization)
        float inv0 = 1.0f / l0, inv1 = 1.0f / l1;
        bool st0 = (Ts[rr0] == c), st1 = (Ts[rr8] == c);
        if (st0 || st1) {
            #pragma unroll
            for (int dt = 0; dt < 8; dt++) {
                int d2 = dt * 8 + (lane & 3) * 2;
                int wofs = (h * 2 + (d2 >> 5)) * 32 + ((d2 & 31) >> 1);
                if (st0) {
                    float q0, q1;
                    unsigned int hi = bfpack2(o[dt][0] * inv0, o[dt][1] * inv0, q0, q1);
                    unsigned int lo = bfpack2n(q0, q1);
                    size_t idx = (size_t)(gq0 + rr0) * 1024 + wofs;
                    aop[idx] = hi; aop[idx + 16] = lo;
                }
                if (st1) {
                    float q0, q1;
                    unsigned int hi = bfpack2(o[dt][2] * inv1, o[dt][3] * inv1, q0, q1);
                    unsigned int lo = bfpack2n(q0, q1);
                    size_t idx = (size_t)(gq0 + rr8) * 1024 + wofs;
                    aop[idx] = hi; aop[idx + 16] = lo;
                }
            }
        }
    }
}

// ------------------------------- launcher ---------------------------------
extern "C" void kernel_launch(void* const* d_in, const int* in_sizes, int n_in,
                              void* d_out, int out_size) {
    const float*         x     = (const float*)d_in[0];
    const float*         media = (const float*)d_in[1];
    const unsigned char* locs  = (const unsigned char*)d_in[2];
    const float*         gamma = (const float*)d_in[3];
    const float*         beta  = (const float*)d_in[4];
    const float*         Wq    = (const float*)d_in[5];
    const float*         Wkv   = (const float*)d_in[6];
    const float*         Wout  = (const float*)d_in[7];
    float*               out   = (float*)d_out;

    unsigned int *xnp, *medp, *aop, *wqt, *wkvt, *woutt, *qp, *kvp;
    int *ttb;
    cudaGetSymbolAddress((void**)&xnp,   g_xnp);
    cudaGetSymbolAddress((void**)&medp,  g_medp);
    cudaGetSymbolAddress((void**)&aop,   g_aop);
    cudaGetSymbolAddress((void**)&wqt,   g_wqt);
    cudaGetSymbolAddress((void**)&wkvt,  g_wkvt);
    cudaGetSymbolAddress((void**)&woutt, g_woutt);
    cudaGetSymbolAddress((void**)&qp,    g_qp);
    cudaGetSymbolAddress((void**)&kvp,   g_kvp);
    cudaGetSymbolAddress((void**)&ttb,   g_tt);

    static bool attr_done = false;
    if (!attr_done) {
        cudaFuncSetAttribute(k_gemm_qkv, cudaFuncAttributeMaxDynamicSharedMemorySize, GSMEM);
        cudaFuncSetAttribute(k_gemm_out, cudaFuncAttributeMaxDynamicSharedMemorySize, GSMEM);
        cudaFuncSetAttribute(k_attn, cudaFuncAttributeMaxDynamicSharedMemorySize, ATT_SMEM);
        attr_done = true;
    }

    // 5 launches; k_attn sits in the ncu capture slot (4th launch).
    k_pack_all<<<NROWS + KVROWS + 4096, 256>>>(x, gamma, beta, media, Wq, Wkv, Wout,
                                               xnp, medp, wqt, wkvt, woutt);
    k_texttime<<<BATCH, 32>>>(locs, ttb);
    k_gemm_qkv<<<768, 256, GSMEM>>>((const uint4*)xnp,  (const uint4*)wqt,  qp,
                                    (const uint4*)medp, (const uint4*)wkvt, kvp);
    k_attn<<<dim3(64, HEADS), 128, ATT_SMEM>>>(qp, kvp, ttb, aop);
    k_gemm_out<<<256, 256, GSMEM>>>((const uint4*)aop, (const uint4*)woutt, out);
}

// round 14
// speedup vs baseline: 1.0963x; 1.0200x over previous
#include <cuda_runtime.h>
#include <cuda_bf16.h>
#include <cstdint>

// ---------------------------------------------------------------------------
// MaskedCrossAttention — round 14: attention fill/compute overlap.
//  * K and V in separate cp.async commit groups: wait K -> QK -> softmax ->
//    wait V -> PV  (V fill overlaps QK+softmax).
//  * First half's K/V prefetched during Q-frag loads / zero-stores.
//  * Q-in-registers, trans-V PV, exp2 softmax (validated R13 structure).
// GEMMs / packs identical to rounds 9-13.
// bf16 hi/lo split math: D = AhBh + AhBl + AlBh (err ~1.8e-5).
// ---------------------------------------------------------------------------

#define BATCH   2
#define TTEXT   2048
#define DIM_    1024
#define TMEDIA  8
#define MTOK    256
#define HEADS   16
#define DHEAD   64
#define INNER   1024
#define NROWS   (BATCH * TTEXT)
#define KVROWS  (BATCH * TMEDIA * MTOK)
#define SCALE_  0.125f
#define SCALE2_ 0.18033688011112042f   /* 0.125 * log2(e) */
#define KDIM    1024

// ------------------------------- scratch ----------------------------------
__device__ unsigned int g_xnp   [NROWS  * KDIM];
__device__ unsigned int g_medp  [KVROWS * KDIM];
__device__ unsigned int g_aop   [NROWS  * KDIM];
__device__ unsigned int g_wqt   [INNER      * KDIM];
__device__ unsigned int g_wkvt  [2 * INNER  * KDIM];
__device__ unsigned int g_woutt [DIM_       * KDIM];
__device__ unsigned int g_qp    [NROWS  * INNER];
__device__ unsigned int g_kvp   [KVROWS * 2 * INNER];
__device__ int          g_tt[NROWS];

// --------------------------- helpers ---------------------------------------
__device__ __forceinline__ uint32_t smem_u32(const void* p) {
    uint32_t a;
    asm("{ .reg .u64 t; cvta.to.shared.u64 t, %1; cvt.u32.u64 %0, t; }" : "=r"(a) : "l"(p));
    return a;
}
#define SWZ128(o) ((o) ^ (((o) >> 3) & 0x70))

#define CP_ASYNC16(dst, src) \
    asm volatile("cp.async.cg.shared.global [%0], [%1], 16;" :: "r"(dst), "l"(src) : "memory")
#define CP_COMMIT() asm volatile("cp.async.commit_group;" ::: "memory")
#define CP_WAIT0()  asm volatile("cp.async.wait_group 0;" ::: "memory")
#define CP_WAIT1()  asm volatile("cp.async.wait_group 1;" ::: "memory")

#define LDSM4(r, addr)                                                        \
    asm volatile("ldmatrix.sync.aligned.m8n8.x4.shared.b16 {%0,%1,%2,%3}, [%4];" \
        : "=r"((r)[0]), "=r"((r)[1]), "=r"((r)[2]), "=r"((r)[3]) : "r"(addr))

#define LDSM4T(r, addr)                                                       \
    asm volatile("ldmatrix.sync.aligned.m8n8.x4.trans.shared.b16 {%0,%1,%2,%3}, [%4];" \
        : "=r"((r)[0]), "=r"((r)[1]), "=r"((r)[2]), "=r"((r)[3]) : "r"(addr))

#define MMA16816(d, a, b)                                                     \
    asm volatile("mma.sync.aligned.m16n8k16.row.col.f32.bf16.bf16.f32 "       \
        "{%0,%1,%2,%3}, {%4,%5,%6,%7}, {%8,%9}, {%0,%1,%2,%3};"               \
        : "+f"((d)[0]), "+f"((d)[1]), "+f"((d)[2]), "+f"((d)[3])              \
        : "r"((a)[0]), "r"((a)[1]), "r"((a)[2]), "r"((a)[3]),                 \
          "r"((b)[0]), "r"((b)[1]))

__device__ __forceinline__ float ex2f_(float x) {
    float y;
    asm("ex2.approx.f32 %0, %1;" : "=f"(y) : "f"(x));
    return y;
}

// ----------------------------- split helpers --------------------------------
__device__ __forceinline__ unsigned int bfpack2(float a, float b, float& ra, float& rb) {
    __nv_bfloat16 ha = __float2bfloat16(a), hb = __float2bfloat16(b);
    ra = a - __bfloat162float(ha);
    rb = b - __bfloat162float(hb);
    unsigned short xa = ((__nv_bfloat16_raw)ha).x, xb = ((__nv_bfloat16_raw)hb).x;
    return (unsigned int)xa | ((unsigned int)xb << 16);
}
__device__ __forceinline__ unsigned int bfpack2n(float a, float b) {
    __nv_bfloat16 ha = __float2bfloat16(a), hb = __float2bfloat16(b);
    unsigned short xa = ((__nv_bfloat16_raw)ha).x, xb = ((__nv_bfloat16_raw)hb).x;
    return (unsigned int)xa | ((unsigned int)xb << 16);
}
__device__ __forceinline__ void split4(float4 v, uint2& H, uint2& L) {
    float r0, r1, r2, r3;
    H.x = bfpack2(v.x, v.y, r0, r1);
    H.y = bfpack2(v.z, v.w, r2, r3);
    L.x = bfpack2n(r0, r1);
    L.y = bfpack2n(r2, r3);
}

// --------------------------- text_time cumsum -----------------------------
__global__ void k_texttime(const unsigned char* __restrict__ locs_raw,
                           int* __restrict__ tt) {
    int b = blockIdx.x;
    int lane = threadIdx.x;
    int cnt = 0;
    for (int i = lane; i < BATCH * TTEXT; i += 32) cnt += (locs_raw[i] != 0);
    #pragma unroll
    for (int off = 16; off; off >>= 1) cnt += __shfl_xor_sync(0xffffffffu, cnt, off);
    bool bytemode = (cnt >= 12);

    const int seg = TTEXT / 32;
    int base = b * TTEXT + lane * seg;
    int s = 0;
    if (bytemode) { for (int i = 0; i < seg; i++) s += (locs_raw[base + i] != 0); }
    else { const int* li = (const int*)locs_raw; for (int i = 0; i < seg; i++) s += (li[base + i] != 0); }
    int inc = s;
    #pragma unroll
    for (int off = 1; off < 32; off <<= 1) {
        int v = __shfl_up_sync(0xffffffffu, inc, off);
        if (lane >= off) inc += v;
    }
    int run = inc - s;
    int* o = tt + base;
    if (bytemode) { for (int i = 0; i < seg; i++) { run += (locs_raw[base + i] != 0); o[i] = run; } }
    else { const int* li = (const int*)locs_raw; for (int i = 0; i < seg; i++) { run += (li[base + i] != 0); o[i] = run; } }
}

// --------------------- fused pack: LN rows + media rows + weights -----------
__device__ __forceinline__ void wpack_tile(const float* __restrict__ W,
                                           unsigned int* __restrict__ out,
                                           int N, int bx, int by) {
    __shared__ float t[32][33];
    int tid = threadIdx.x;
    int k0 = by * 32, n0 = bx * 32;
    {
        int kr = tid >> 3, f4 = (tid & 7) * 4;
        float4 v = *(const float4*)&W[(size_t)(k0 + kr) * N + n0 + f4];
        t[f4 + 0][kr] = v.x; t[f4 + 1][kr] = v.y; t[f4 + 2][kr] = v.z; t[f4 + 3][kr] = v.w;
    }
    __syncthreads();
    {
        int n = tid >> 3, kq = (tid & 7) * 4;
        float4 u = make_float4(t[n][kq], t[n][kq + 1], t[n][kq + 2], t[n][kq + 3]);
        uint2 H, L;
        split4(u, H, L);
        size_t idx = (size_t)(n0 + n) * KDIM + (k0 >> 5) * 32 + (kq >> 1);
        *(uint2*)&out[idx]      = H;
        *(uint2*)&out[idx + 16] = L;
    }
}

__global__ __launch_bounds__(256) void k_pack_all(
        const float* __restrict__ x,
        const float* __restrict__ gamma,
        const float* __restrict__ beta,
        const float* __restrict__ media,
        const float* __restrict__ Wq,
        const float* __restrict__ Wkv,
        const float* __restrict__ Wout,
        unsigned int* __restrict__ xnp,
        unsigned int* __restrict__ medp,
        unsigned int* __restrict__ wqt,
        unsigned int* __restrict__ wkvt,
        unsigned int* __restrict__ woutt) {
    int bid = blockIdx.x;
    int tid = threadIdx.x;
    if (bid < NROWS) {
        int row = bid;
        const float4* xr = (const float4*)(x + (size_t)row * DIM_);
        float4 v = xr[tid];
        float s = v.x + v.y + v.z + v.w;
        float q = v.x * v.x + v.y * v.y + v.z * v.z + v.w * v.w;
        __shared__ float ss[8], sq[8];
        #pragma unroll
        for (int off = 16; off; off >>= 1) {
            s += __shfl_xor_sync(0xffffffffu, s, off);
            q += __shfl_xor_sync(0xffffffffu, q, off);
        }
        int w = tid >> 5, l = tid & 31;
        if (l == 0) { ss[w] = s; sq[w] = q; }
        __syncthreads();
        if (w == 0) {
            s = (l < 8) ? ss[l] : 0.f;
            q = (l < 8) ? sq[l] : 0.f;
            #pragma unroll
            for (int off = 4; off; off >>= 1) {
                s += __shfl_xor_sync(0xffffffffu, s, off);
                q += __shfl_xor_sync(0xffffffffu, q, off);
            }
            if (l == 0) { ss[0] = s; sq[0] = q; }
        }
        __syncthreads();
        float mu   = ss[0] * (1.0f / DIM_);
        float var  = sq[0] * (1.0f / DIM_) - mu * mu;
        float rstd = rsqrtf(var + 1e-5f);
        float4 g  = ((const float4*)gamma)[tid];
        float4 bb = ((const float4*)beta)[tid];
        float4 o;
        o.x = (v.x - mu) * rstd * g.x + bb.x;
        o.y = (v.y - mu) * rstd * g.y + bb.y;
        o.z = (v.z - mu) * rstd * g.z + bb.z;
        o.w = (v.w - mu) * rstd * g.w + bb.w;
        uint2 H, L;
        split4(o, H, L);
        size_t idx = (size_t)row * KDIM + (tid >> 3) * 32 + (tid & 7) * 2;
        *(uint2*)&xnp[idx]      = H;
        *(uint2*)&xnp[idx + 16] = L;
    } else if (bid < NROWS + KVROWS) {
        int row = bid - NROWS;
        float4 v = ((const float4*)(media + (size_t)row * KDIM))[tid];
        uint2 H, L;
        split4(v, H, L);
        size_t idx = (size_t)row * KDIM + (tid >> 3) * 32 + (tid & 7) * 2;
        *(uint2*)&medp[idx]      = H;
        *(uint2*)&medp[idx + 16] = L;
    } else {
        int wb = bid - (NROWS + KVROWS);
        if (wb < 1024) {
            wpack_tile(Wq, wqt, INNER, wb & 31, wb >> 5);
        } else if (wb < 3072) {
            int b2 = wb - 1024;
            wpack_tile(Wkv, wkvt, 2 * INNER, b2 & 63, b2 >> 6);
        } else {
            int b3 = wb - 3072;
            wpack_tile(Wout, woutt, DIM_, b3 & 31, b3 >> 5);
        }
    }
}

// --------------------- warp-MMA split-bf16 GEMM body ------------------------
#define GSTAGE_B   32768
#define GSTAGES    3
#define STAGE_ROWB 528
#define GSMEM      (GSTAGES * GSTAGE_B)

template <bool PACK>
__device__ __forceinline__ void gemm_body(const uint4* __restrict__ A,
                                          const uint4* __restrict__ B,
                                          void* __restrict__ Cout,
                                          int N, int bx, int by, char* sm) {
    const int tid = threadIdx.x, wid = tid >> 5, lane = tid & 31;
    const uint32_t smb = smem_u32(sm);
    const int rowb = by * 128, colb = bx * 128;
    const int warp_m = wid >> 2, warp_n = wid & 3;
    const int r = tid >> 3, sgi = tid & 7;
    const uint4* Ab = A + (size_t)rowb * 256;
    const uint4* Bb = B + (size_t)colb * 256;

    const int arow_l = (lane & 7) + ((lane >> 3) & 1) * 8;
    const int acol_l = (lane >> 4) * 16;
    const int brow_l = (lane & 7) + (lane >> 4) * 8;
    const int bcol_l = ((lane >> 3) & 1) * 16;

    float acc[4][4][4];
    #pragma unroll
    for (int mt = 0; mt < 4; mt++)
        #pragma unroll
        for (int nt = 0; nt < 4; nt++)
            #pragma unroll
            for (int e = 0; e < 4; e++) acc[mt][nt][e] = 0.f;

    #pragma unroll
    for (int c0 = 0; c0 < 2; c0++) {
        uint32_t stp = smb + c0 * GSTAGE_B;
        #pragma unroll
        for (int it = 0; it < 4; it++) {
            int rr = r + it * 32;
            uint32_t so = SWZ128(rr * 128 + sgi * 16);
            CP_ASYNC16(stp + so,         (const void*)(Ab + (size_t)rr * 256 + c0 * 8 + sgi));
            CP_ASYNC16(stp + 16384 + so, (const void*)(Bb + (size_t)rr * 256 + c0 * 8 + sgi));
        }
        CP_COMMIT();
    }
    CP_WAIT1();
    __syncthreads();

    for (int c = 0; c < 32; c++) {
        uint32_t stb = smb + (c % GSTAGES) * GSTAGE_B;
        if (c + 2 < 32) {
            uint32_t nstb = smb + ((c + 2) % GSTAGES) * GSTAGE_B;
            #pragma unroll
            for (int it = 0; it < 4; it++) {
                int rr = r + it * 32;
                uint32_t so = SWZ128(rr * 128 + sgi * 16);
                CP_ASYNC16(nstb + so,         (const void*)(Ab + (size_t)rr * 256 + (c + 2) * 8 + sgi));
                CP_ASYNC16(nstb + 16384 + so, (const void*)(Bb + (size_t)rr * 256 + (c + 2) * 8 + sgi));
            }
            CP_COMMIT();
        }

        #pragma unroll
        for (int s = 0; s < 2; s++) {
            const int kbh = s * 32, kbl = 64 + s * 32;
            uint32_t bh[2][4], bl[2][4];
            #pragma unroll
            for (int p = 0; p < 2; p++) {
                int bb = 16384 + (warp_n * 32 + p * 16 + brow_l) * 128 + bcol_l;
                LDSM4(bh[p], stb + SWZ128(bb + kbh));
                LDSM4(bl[p], stb + SWZ128(bb + kbl));
            }
            #pragma unroll
            for (int mt = 0; mt < 4; mt++) {
                uint32_t ah[4], al[4];
                int ab = (warp_m * 64 + mt * 16 + arow_l) * 128 + acol_l;
                LDSM4(ah, stb + SWZ128(ab + kbh));
                LDSM4(al, stb + SWZ128(ab + kbl));
                #pragma unroll
                for (int nt = 0; nt < 4; nt++) {
                    MMA16816(acc[mt][nt], ah, &bh[nt >> 1][(nt & 1) * 2]);
                    MMA16816(acc[mt][nt], ah, &bl[nt >> 1][(nt & 1) * 2]);
                    MMA16816(acc[mt][nt], al, &bh[nt >> 1][(nt & 1) * 2]);
                }
            }
        }
        if (c + 1 < 32) {
            if (c + 2 < 32) { CP_WAIT1(); } else { CP_WAIT0(); }
        }
        __syncthreads();
    }

    #pragma unroll
    for (int mt = 0; mt < 4; mt++) {
        #pragma unroll
        for (int hf = 0; hf < 2; hf++) {
            int r0 = warp_m * 64 + mt * 16 + hf * 8 + (lane >> 2);
            #pragma unroll
            for (int nt = 0; nt < 4; nt++) {
                int cl = warp_n * 32 + nt * 8 + (lane & 3) * 2;
                if (PACK) {
                    float rr0, rr1;
                    unsigned int hi = bfpack2(acc[mt][nt][hf * 2], acc[mt][nt][hf * 2 + 1], rr0, rr1);
                    unsigned int lo = bfpack2n(rr0, rr1);
                    int wl = (cl >> 5) * 32 + ((cl & 31) >> 1);
                    *(unsigned int*)(sm + r0 * STAGE_ROWB + wl * 4)      = hi;
                    *(unsigned int*)(sm + r0 * STAGE_ROWB + wl * 4 + 64) = lo;
                } else {
                    *(float2*)(sm + r0 * STAGE_ROWB + cl * 4) =
                        make_float2(acc[mt][nt][hf * 2], acc[mt][nt][hf * 2 + 1]);
                }
            }
        }
    }
    __syncthreads();
    char* Cb = (char*)Cout;
    #pragma unroll
    for (int i = 0; i < 16; i++) {
        int idx = tid + i * 256;
        int row = idx >> 5, ch = idx & 31;
        uint4 v = *(uint4*)(sm + row * STAGE_ROWB + ch * 16);
        *(uint4*)(Cb + ((size_t)(rowb + row) * N + colb + ch * 4) * 4) = v;
    }
}

__global__ __launch_bounds__(256, 2) void k_gemm_qkv(const uint4* __restrict__ Aq,
                                                     const uint4* __restrict__ Bq,
                                                     unsigned int* __restrict__ Cq,
                                                     const uint4* __restrict__ Akv,
                                                     const uint4* __restrict__ Bkv,
                                                     unsigned int* __restrict__ Ckv) {
    extern __shared__ __align__(1024) char sm[];
    int bid = blockIdx.x;
    if (bid < 256) {
        gemm_body<true>(Aq, Bq, Cq, INNER, bid & 7, bid >> 3, sm);
    } else {
        int b2 = bid - 256;
        gemm_body<true>(Akv, Bkv, Ckv, 2 * INNER, b2 & 15, b2 >> 4, sm);
    }
}

__global__ __launch_bounds__(256, 2) void k_gemm_out(const uint4* __restrict__ A,
                                                     const uint4* __restrict__ B,
                                                     float* __restrict__ C) {
    extern __shared__ __align__(1024) char sm[];
    int bid = blockIdx.x;
    gemm_body<false>(A, B, C, DIM_, bid & 7, bid >> 3, sm);
}

// ------------------- attention (Q-in-regs, split K/V waits) -----------------
// grid (64 q-tiles, 16 heads); block 128 (4 warps, M-split 16 rows/warp).
// SMEM: K 2x16384 @0 | V 2x16384 @32768 | Ts @65536.
#define ATT_K    0
#define ATT_V    32768
#define ATT_TS   65536
#define ATT_SMEM (ATT_TS + 256)

// Issue K (commit group) then V (commit group) cp.async fills for one 128-key half.
__device__ __forceinline__ void attn_fill(uint32_t smb, const unsigned int* __restrict__ kvp,
                                          int kbase, int h, int tid) {
    #pragma unroll
    for (int it = 0; it < 16; it++) {
        int t = tid + it * 128;
        int row = t >> 4, rest = t & 15;
        int panel = rest >> 3, q4 = rest & 7;
        uint32_t so = SWZ128(row * 128 + q4 * 16);
        CP_ASYNC16(smb + ATT_K + panel * 16384 + so,
                   (const void*)&kvp[(size_t)(kbase + row) * 2048 + (h * 2 + panel) * 32 + q4 * 4]);
    }
    CP_COMMIT();
    #pragma unroll
    for (int it = 0; it < 16; it++) {
        int t = tid + it * 128;
        int row = t >> 4, rest = t & 15;
        int panel = rest >> 3, q4 = rest & 7;
        uint32_t so = SWZ128(row * 128 + q4 * 16);
        CP_ASYNC16(smb + ATT_V + panel * 16384 + so,
                   (const void*)&kvp[(size_t)(kbase + row) * 2048 + (32 + h * 2 + panel) * 32 + q4 * 4]);
    }
    CP_COMMIT();
}

__global__ __launch_bounds__(128, 3) void k_attn(const unsigned int* __restrict__ qp,
                                                 const unsigned int* __restrict__ kvp,
                                                 const int* __restrict__ tt,
                                                 unsigned int* __restrict__ aop) {
    extern __shared__ __align__(1024) char sm[];
    const uint32_t smb = smem_u32(sm);
    const int tid = threadIdx.x, w = tid >> 5, lane = tid & 31;
    const int tile = blockIdx.x, h = blockIdx.y;
    const int gq0 = tile * 64;
    const int b = gq0 >> 11;

    const int brow_l = (lane & 7) + (lane >> 4) * 8;
    const int bcol_l = ((lane >> 3) & 1) * 16;

    int* Ts = (int*)(sm + ATT_TS);
    if (tid < 64) Ts[tid] = tt[gq0 + tid];

    const int rr0 = w * 16 + (lane >> 2);
    const int rr8 = rr0 + 8;

    __syncthreads();   // Ts visible
    int c0 = Ts[0] < 1 ? 1 : Ts[0];
    int c1 = Ts[63];

    // ---- prefetch first half's K/V (overlaps Q loads + zero stores below)
    if (c0 <= c1)
        attn_fill(smb, kvp, b * (TMEDIA * MTOK) + (c0 - 1) * MTOK, h, tid);

    // ---- Q fragments direct from packed global: qh/ql[kstep][a0..a3]
    uint32_t qh[4][4], ql[4][4];
    {
        const unsigned int* q0p = qp + (size_t)(gq0 + rr0) * 1024 + h * 64;
        const unsigned int* q8p = qp + (size_t)(gq0 + rr8) * 1024 + h * 64;
        #pragma unroll
        for (int ks = 0; ks < 4; ks++) {
            int off = (ks >> 1) * 32 + (ks & 1) * 8 + (lane & 3);
            qh[ks][0] = q0p[off];      qh[ks][1] = q8p[off];
            qh[ks][2] = q0p[off + 4];  qh[ks][3] = q8p[off + 4];
            ql[ks][0] = q0p[off + 16]; ql[ks][1] = q8p[off + 16];
            ql[ks][2] = q0p[off + 20]; ql[ks][3] = q8p[off + 20];
        }
    }

    // ---- zero rows with text_time == 0 (this head's 64-word segment)
    #pragma unroll
    for (int it = 0; it < 8; it++) {
        int slot = tid + it * 128;
        int row = slot >> 4, w4 = slot & 15;
        if (Ts[row] == 0)
            *(uint4*)&aop[(size_t)(gq0 + row) * 1024 + h * 64 + w4 * 4] =
                make_uint4(0, 0, 0, 0);
    }

    // ldmatrix.trans lane addressing for PV B-frags
    const int t_midx = lane >> 3, t_lrow = lane & 7;
    const int t_tok_off = (t_midx & 1) * 8 + t_lrow;
    const int t_seg     = (t_midx >> 1) * 16;

    bool first = true;
    for (int c = c0; c <= c1; c++) {
        float o[8][4];
        #pragma unroll
        for (int dt = 0; dt < 8; dt++)
            #pragma unroll
            for (int e = 0; e < 4; e++) o[dt][e] = 0.f;
        float pm0 = -1e30f, pm1 = -1e30f, l0 = 0.f, l1 = 0.f;

        #pragma unroll
        for (int hx = 0; hx < 2; hx++) {
            const int kbase = b * (TMEDIA * MTOK) + (c - 1) * MTOK + hx * 128;
            if (!first) {
                __syncthreads();   // prior K/V reads complete
                attn_fill(smb, kvp, kbase, h, tid);
            }
            first = false;
            CP_WAIT1();            // K group complete (V still in flight)
            __syncthreads();

            // ---- QK^T: warp tile M=16, N=128, K=64 (split x3), Q from regs
            float acc[16][4];
            #pragma unroll
            for (int nt = 0; nt < 16; nt++)
                #pragma unroll
                for (int e = 0; e < 4; e++) acc[nt][e] = 0.f;

            #pragma unroll
            for (int cc = 0; cc < 2; cc++) {
                uint32_t kb = smb + ATT_K + cc * 16384;
                #pragma unroll
                for (int s = 0; s < 2; s++) {
                    const int kstep = cc * 2 + s;
                    const int kbh = s * 32, kbl = 64 + s * 32;
                    #pragma unroll
                    for (int p4 = 0; p4 < 2; p4++) {
                        uint32_t bh[4][4], bl[4][4];
                        #pragma unroll
                        for (int p = 0; p < 4; p++) {
                            int bb = ((p4 * 4 + p) * 16 + brow_l) * 128 + bcol_l;
                            LDSM4(bh[p], kb + SWZ128(bb + kbh));
                            LDSM4(bl[p], kb + SWZ128(bb + kbl));
                        }
                        #pragma unroll
                        for (int nt = 0; nt < 8; nt++) {
                            float* d = acc[p4 * 8 + nt];
                            MMA16816(d, qh[kstep], &bh[nt >> 1][(nt & 1) * 2]);
                            MMA16816(d, qh[kstep], &bl[nt >> 1][(nt & 1) * 2]);
                            MMA16816(d, ql[kstep], &bh[nt >> 1][(nt & 1) * 2]);
                        }
                    }
                }
            }

            // ---- online softmax in exp2 domain (regs only — overlaps V fill)
            float m0 = -1e30f, m1 = -1e30f;
            #pragma unroll
            for (int nt = 0; nt < 16; nt++) {
                acc[nt][0] *= SCALE2_; acc[nt][1] *= SCALE2_;
                acc[nt][2] *= SCALE2_; acc[nt][3] *= SCALE2_;
                m0 = fmaxf(m0, fmaxf(acc[nt][0], acc[nt][1]));
                m1 = fmaxf(m1, fmaxf(acc[nt][2], acc[nt][3]));
            }
            m0 = fmaxf(m0, __shfl_xor_sync(0xffffffffu, m0, 1));
            m0 = fmaxf(m0, __shfl_xor_sync(0xffffffffu, m0, 2));
            m1 = fmaxf(m1, __shfl_xor_sync(0xffffffffu, m1, 1));
            m1 = fmaxf(m1, __shfl_xor_sync(0xffffffffu, m1, 2));
            float n0 = fmaxf(pm0, m0), n1 = fmaxf(pm1, m1);
            float a0 = ex2f_(pm0 - n0), a1 = ex2f_(pm1 - n1);
            #pragma unroll
            for (int dt = 0; dt < 8; dt++) {
                o[dt][0] *= a0; o[dt][1] *= a0;
                o[dt][2] *= a1; o[dt][3] *= a1;
            }
            float s0 = 0.f, s1 = 0.f;
            #pragma unroll
            for (int nt = 0; nt < 16; nt++) {
                float e0 = ex2f_(acc[nt][0] - n0), e1 = ex2f_(acc[nt][1] - n0);
                float e2 = ex2f_(acc[nt][2] - n1), e3 = ex2f_(acc[nt][3] - n1);
                acc[nt][0] = e0; acc[nt][1] = e1; acc[nt][2] = e2; acc[nt][3] = e3;
                s0 += e0 + e1; s1 += e2 + e3;
            }
            s0 += __shfl_xor_sync(0xffffffffu, s0, 1);
            s0 += __shfl_xor_sync(0xffffffffu, s0, 2);
            s1 += __shfl_xor_sync(0xffffffffu, s1, 1);
            s1 += __shfl_xor_sync(0xffffffffu, s1, 2);
            l0 = l0 * a0 + s0; l1 = l1 * a1 + s1;
            pm0 = n0; pm1 = n1;

            // ---- V ready? then PV (P from registers; V frags via ldmatrix.trans)
            CP_WAIT0();
            __syncthreads();

            #pragma unroll
            for (int ks = 0; ks < 8; ks++) {
                uint32_t aph[4], apl[4];
                float q0, q1;
                aph[0] = bfpack2(acc[2 * ks][0],     acc[2 * ks][1],     q0, q1);
                apl[0] = bfpack2n(q0, q1);
                aph[1] = bfpack2(acc[2 * ks][2],     acc[2 * ks][3],     q0, q1);
                apl[1] = bfpack2n(q0, q1);
                aph[2] = bfpack2(acc[2 * ks + 1][0], acc[2 * ks + 1][1], q0, q1);
                apl[2] = bfpack2n(q0, q1);
                aph[3] = bfpack2(acc[2 * ks + 1][2], acc[2 * ks + 1][3], q0, q1);
                apl[3] = bfpack2n(q0, q1);

                int token = ks * 16 + t_tok_off;
                #pragma unroll
                for (int d16 = 0; d16 < 4; d16++) {
                    uint32_t vb = smb + ATT_V + (d16 >> 1) * 16384;
                    int boff = (d16 & 1) * 32 + t_seg;
                    uint32_t bvh4[4], bvl4[4];
                    LDSM4T(bvh4, vb + SWZ128(token * 128 + boff));
                    LDSM4T(bvl4, vb + SWZ128(token * 128 + 64 + boff));
                    #pragma unroll
                    for (int dt2 = 0; dt2 < 2; dt2++) {
                        int dt = d16 * 2 + dt2;
                        MMA16816(o[dt], aph, &bvh4[dt2 * 2]);
                        MMA16816(o[dt], aph, &bvl4[dt2 * 2]);
                        MMA16816(o[dt], apl, &bvh4[dt2 * 2]);
                    }
                }
            }
        }

        // ---- store rows belonging to this chunk (deferred normalization)
        float inv0 = 1.0f / l0, inv1 = 1.0f / l1;
        bool st0 = (Ts[rr0] == c), st1 = (Ts[rr8] == c);
        if (st0 || st1) {
            #pragma unroll
            for (int dt = 0; dt < 8; dt++) {
                int d2 = dt * 8 + (lane & 3) * 2;
                int wofs = (h * 2 + (d2 >> 5)) * 32 + ((d2 & 31) >> 1);
                if (st0) {
                    float q0, q1;
                    unsigned int hi = bfpack2(o[dt][0] * inv0, o[dt][1] * inv0, q0, q1);
                    unsigned int lo = bfpack2n(q0, q1);
                    size_t idx = (size_t)(gq0 + rr0) * 1024 + wofs;
                    aop[idx] = hi; aop[idx + 16] = lo;
                }
                if (st1) {
                    float q0, q1;
                    unsigned int hi = bfpack2(o[dt][2] * inv1, o[dt][3] * inv1, q0, q1);
                    unsigned int lo = bfpack2n(q0, q1);
                    size_t idx = (size_t)(gq0 + rr8) * 1024 + wofs;
                    aop[idx] = hi; aop[idx + 16] = lo;
                }
            }
        }
    }
}

// ------------------------------- launcher ---------------------------------
extern "C" void kernel_launch(void* const* d_in, const int* in_sizes, int n_in,
                              void* d_out, int out_size) {
    const float*         x     = (const float*)d_in[0];
    const float*         media = (const float*)d_in[1];
    const unsigned char* locs  = (const unsigned char*)d_in[2];
    const float*         gamma = (const float*)d_in[3];
    const float*         beta  = (const float*)d_in[4];
    const float*         Wq    = (const float*)d_in[5];
    const float*         Wkv   = (const float*)d_in[6];
    const float*         Wout  = (const float*)d_in[7];
    float*               out   = (float*)d_out;

    unsigned int *xnp, *medp, *aop, *wqt, *wkvt, *woutt, *qp, *kvp;
    int *ttb;
    cudaGetSymbolAddress((void**)&xnp,   g_xnp);
    cudaGetSymbolAddress((void**)&medp,  g_medp);
    cudaGetSymbolAddress((void**)&aop,   g_aop);
    cudaGetSymbolAddress((void**)&wqt,   g_wqt);
    cudaGetSymbolAddress((void**)&wkvt,  g_wkvt);
    cudaGetSymbolAddress((void**)&woutt, g_woutt);
    cudaGetSymbolAddress((void**)&qp,    g_qp);
    cudaGetSymbolAddress((void**)&kvp,   g_kvp);
    cudaGetSymbolAddress((void**)&ttb,   g_tt);

    static bool attr_done = false;
    if (!attr_done) {
        cudaFuncSetAttribute(k_gemm_qkv, cudaFuncAttributeMaxDynamicSharedMemorySize, GSMEM);
        cudaFuncSetAttribute(k_gemm_out, cudaFuncAttributeMaxDynamicSharedMemorySize, GSMEM);
        cudaFuncSetAttribute(k_attn, cudaFuncAttributeMaxDynamicSharedMemorySize, ATT_SMEM);
        attr_done = true;
    }

    // 5 launches; k_attn sits in the ncu capture slot (4th launch).
    k_pack_all<<<NROWS + KVROWS + 4096, 256>>>(x, gamma, beta, media, Wq, Wkv, Wout,
                                               xnp, medp, wqt, wkvt, woutt);
    k_texttime<<<BATCH, 32>>>(locs, ttb);
    k_gemm_qkv<<<768, 256, GSMEM>>>((const uint4*)xnp,  (const uint4*)wqt,  qp,
                                    (const uint4*)medp, (const uint4*)wkvt, kvp);
    k_attn<<<dim3(64, HEADS), 128, ATT_SMEM>>>(qp, kvp, ttb, aop);
    k_gemm_out<<<256, 256, GSMEM>>>((const uint4*)aop, (const uint4*)woutt, out);
}

// round 15
// speedup vs baseline: 1.1281x; 1.0290x over previous
#include <cuda_runtime.h>
#include <cuda_bf16.h>
#include <cstdint>

// ---------------------------------------------------------------------------
// MaskedCrossAttention — round 15: serial-phase trim.
//  * softmax scale folded into Wq pack (QK logits arrive in exp2 domain)
//  * bf16 pair packing via single cvt.rn.bf16x2.f32 (+ shift/mask upcasts)
//  * k_texttime merged into k_pack_all (4 launches total)
//  * attention structure identical to round 14 (Q-in-regs, split K/V waits)
// bf16 hi/lo split math: D = AhBh + AhBl + AlBh (err ~1.8e-5).
// ---------------------------------------------------------------------------

#define BATCH   2
#define TTEXT   2048
#define DIM_    1024
#define TMEDIA  8
#define MTOK    256
#define HEADS   16
#define DHEAD   64
#define INNER   1024
#define NROWS   (BATCH * TTEXT)
#define KVROWS  (BATCH * TMEDIA * MTOK)
#define SCALE2_ 0.18033688011112042f   /* 0.125 * log2(e), folded into Wq */
#define KDIM    1024

// ------------------------------- scratch ----------------------------------
__device__ unsigned int g_xnp   [NROWS  * KDIM];
__device__ unsigned int g_medp  [KVROWS * KDIM];
__device__ unsigned int g_aop   [NROWS  * KDIM];
__device__ unsigned int g_wqt   [INNER      * KDIM];
__device__ unsigned int g_wkvt  [2 * INNER  * KDIM];
__device__ unsigned int g_woutt [DIM_       * KDIM];
__device__ unsigned int g_qp    [NROWS  * INNER];
__device__ unsigned int g_kvp   [KVROWS * 2 * INNER];
__device__ int          g_tt[NROWS];

// --------------------------- helpers ---------------------------------------
__device__ __forceinline__ uint32_t smem_u32(const void* p) {
    uint32_t a;
    asm("{ .reg .u64 t; cvta.to.shared.u64 t, %1; cvt.u32.u64 %0, t; }" : "=r"(a) : "l"(p));
    return a;
}
#define SWZ128(o) ((o) ^ (((o) >> 3) & 0x70))

#define CP_ASYNC16(dst, src) \
    asm volatile("cp.async.cg.shared.global [%0], [%1], 16;" :: "r"(dst), "l"(src) : "memory")
#define CP_COMMIT() asm volatile("cp.async.commit_group;" ::: "memory")
#define CP_WAIT0()  asm volatile("cp.async.wait_group 0;" ::: "memory")
#define CP_WAIT1()  asm volatile("cp.async.wait_group 1;" ::: "memory")

#define LDSM4(r, addr)                                                        \
    asm volatile("ldmatrix.sync.aligned.m8n8.x4.shared.b16 {%0,%1,%2,%3}, [%4];" \
        : "=r"((r)[0]), "=r"((r)[1]), "=r"((r)[2]), "=r"((r)[3]) : "r"(addr))

#define LDSM4T(r, addr)                                                       \
    asm volatile("ldmatrix.sync.aligned.m8n8.x4.trans.shared.b16 {%0,%1,%2,%3}, [%4];" \
        : "=r"((r)[0]), "=r"((r)[1]), "=r"((r)[2]), "=r"((r)[3]) : "r"(addr))

#define MMA16816(d, a, b)                                                     \
    asm volatile("mma.sync.aligned.m16n8k16.row.col.f32.bf16.bf16.f32 "       \
        "{%0,%1,%2,%3}, {%4,%5,%6,%7}, {%8,%9}, {%0,%1,%2,%3};"               \
        : "+f"((d)[0]), "+f"((d)[1]), "+f"((d)[2]), "+f"((d)[3])              \
        : "r"((a)[0]), "r"((a)[1]), "r"((a)[2]), "r"((a)[3]),                 \
          "r"((b)[0]), "r"((b)[1]))

__device__ __forceinline__ float ex2f_(float x) {
    float y;
    asm("ex2.approx.f32 %0, %1;" : "=f"(y) : "f"(x));
    return y;
}

// ----------------------------- split helpers --------------------------------
// Pack (a -> low half, b -> high half) with round-to-nearest in ONE cvt.
__device__ __forceinline__ unsigned int bfpack2n(float a, float b) {
    unsigned int r;
    asm("cvt.rn.bf16x2.f32 %0, %1, %2;" : "=r"(r) : "f"(b), "f"(a));
    return r;
}
__device__ __forceinline__ unsigned int bfpack2(float a, float b, float& ra, float& rb) {
    unsigned int hi = bfpack2n(a, b);
    ra = a - __uint_as_float(hi << 16);          // bf16->f32 upcast = bit shift
    rb = b - __uint_as_float(hi & 0xffff0000u);
    return hi;
}
__device__ __forceinline__ void split4(float4 v, uint2& H, uint2& L) {
    float r0, r1, r2, r3;
    H.x = bfpack2(v.x, v.y, r0, r1);
    H.y = bfpack2(v.z, v.w, r2, r3);
    L.x = bfpack2n(r0, r1);
    L.y = bfpack2n(r2, r3);
}

// --------------------- fused pack: LN + media + weights + texttime ----------
__device__ __forceinline__ void wpack_tile(const float* __restrict__ W,
                                           unsigned int* __restrict__ out,
                                           int N, int bx, int by, float scale) {
    __shared__ float t[32][33];
    int tid = threadIdx.x;
    int k0 = by * 32, n0 = bx * 32;
    {
        int kr = tid >> 3, f4 = (tid & 7) * 4;
        float4 v = *(const float4*)&W[(size_t)(k0 + kr) * N + n0 + f4];
        t[f4 + 0][kr] = v.x * scale; t[f4 + 1][kr] = v.y * scale;
        t[f4 + 2][kr] = v.z * scale; t[f4 + 3][kr] = v.w * scale;
    }
    __syncthreads();
    {
        int n = tid >> 3, kq = (tid & 7) * 4;
        float4 u = make_float4(t[n][kq], t[n][kq + 1], t[n][kq + 2], t[n][kq + 3]);
        uint2 H, L;
        split4(u, H, L);
        size_t idx = (size_t)(n0 + n) * KDIM + (k0 >> 5) * 32 + (kq >> 1);
        *(uint2*)&out[idx]      = H;
        *(uint2*)&out[idx + 16] = L;
    }
}

__global__ __launch_bounds__(256) void k_pack_all(
        const float* __restrict__ x,
        const float* __restrict__ gamma,
        const float* __restrict__ beta,
        const float* __restrict__ media,
        const float* __restrict__ Wq,
        const float* __restrict__ Wkv,
        const float* __restrict__ Wout,
        const unsigned char* __restrict__ locs_raw,
        unsigned int* __restrict__ xnp,
        unsigned int* __restrict__ medp,
        unsigned int* __restrict__ wqt,
        unsigned int* __restrict__ wkvt,
        unsigned int* __restrict__ woutt,
        int* __restrict__ tt) {
    int bid = blockIdx.x;
    int tid = threadIdx.x;
    if (bid < NROWS) {
        int row = bid;
        const float4* xr = (const float4*)(x + (size_t)row * DIM_);
        float4 v = xr[tid];
        float s = v.x + v.y + v.z + v.w;
        float q = v.x * v.x + v.y * v.y + v.z * v.z + v.w * v.w;
        __shared__ float ss[8], sq[8];
        #pragma unroll
        for (int off = 16; off; off >>= 1) {
            s += __shfl_xor_sync(0xffffffffu, s, off);
            q += __shfl_xor_sync(0xffffffffu, q, off);
        }
        int w = tid >> 5, l = tid & 31;
        if (l == 0) { ss[w] = s; sq[w] = q; }
        __syncthreads();
        if (w == 0) {
            s = (l < 8) ? ss[l] : 0.f;
            q = (l < 8) ? sq[l] : 0.f;
            #pragma unroll
            for (int off = 4; off; off >>= 1) {
                s += __shfl_xor_sync(0xffffffffu, s, off);
                q += __shfl_xor_sync(0xffffffffu, q, off);
            }
            if (l == 0) { ss[0] = s; sq[0] = q; }
        }
        __syncthreads();
        float mu   = ss[0] * (1.0f / DIM_);
        float var  = sq[0] * (1.0f / DIM_) - mu * mu;
        float rstd = rsqrtf(var + 1e-5f);
        float4 g  = ((const float4*)gamma)[tid];
        float4 bb = ((const float4*)beta)[tid];
        float4 o;
        o.x = (v.x - mu) * rstd * g.x + bb.x;
        o.y = (v.y - mu) * rstd * g.y + bb.y;
        o.z = (v.z - mu) * rstd * g.z + bb.z;
        o.w = (v.w - mu) * rstd * g.w + bb.w;
        uint2 H, L;
        split4(o, H, L);
        size_t idx = (size_t)row * KDIM + (tid >> 3) * 32 + (tid & 7) * 2;
        *(uint2*)&xnp[idx]      = H;
        *(uint2*)&xnp[idx + 16] = L;
    } else if (bid < NROWS + KVROWS) {
        int row = bid - NROWS;
        float4 v = ((const float4*)(media + (size_t)row * KDIM))[tid];
        uint2 H, L;
        split4(v, H, L);
        size_t idx = (size_t)row * KDIM + (tid >> 3) * 32 + (tid & 7) * 2;
        *(uint2*)&medp[idx]      = H;
        *(uint2*)&medp[idx + 16] = L;
    } else if (bid < NROWS + KVROWS + 4096) {
        int wb = bid - (NROWS + KVROWS);
        if (wb < 1024) {
            wpack_tile(Wq, wqt, INNER, wb & 31, wb >> 5, SCALE2_);  // scale folded
        } else if (wb < 3072) {
            int b2 = wb - 1024;
            wpack_tile(Wkv, wkvt, 2 * INNER, b2 & 63, b2 >> 6, 1.0f);
        } else {
            int b3 = wb - 3072;
            wpack_tile(Wout, woutt, DIM_, b3 & 31, b3 >> 5, 1.0f);
        }
    } else {
        // text_time cumsum: 2 warps, warp b handles batch b
        if (tid < 64) {
            int b = tid >> 5, lane = tid & 31;
            int cnt = 0;
            for (int i = lane; i < BATCH * TTEXT; i += 32) cnt += (locs_raw[i] != 0);
            #pragma unroll
            for (int off = 16; off; off >>= 1) cnt += __shfl_xor_sync(0xffffffffu, cnt, off);
            bool bytemode = (cnt >= 12);
            const int seg = TTEXT / 32;
            int base = b * TTEXT + lane * seg;
            int s = 0;
            if (bytemode) { for (int i = 0; i < seg; i++) s += (locs_raw[base + i] != 0); }
            else { const int* li = (const int*)locs_raw; for (int i = 0; i < seg; i++) s += (li[base + i] != 0); }
            int inc = s;
            #pragma unroll
            for (int off = 1; off < 32; off <<= 1) {
                int v = __shfl_up_sync(0xffffffffu, inc, off);
                if (lane >= off) inc += v;
            }
            int run = inc - s;
            int* o = tt + base;
            if (bytemode) { for (int i = 0; i < seg; i++) { run += (locs_raw[base + i] != 0); o[i] = run; } }
            else { const int* li = (const int*)locs_raw; for (int i = 0; i < seg; i++) { run += (li[base + i] != 0); o[i] = run; } }
        }
    }
}

// --------------------- warp-MMA split-bf16 GEMM body ------------------------
#define GSTAGE_B   32768
#define GSTAGES    3
#define STAGE_ROWB 528
#define GSMEM      (GSTAGES * GSTAGE_B)

template <bool PACK>
__device__ __forceinline__ void gemm_body(const uint4* __restrict__ A,
                                          const uint4* __restrict__ B,
                                          void* __restrict__ Cout,
                                          int N, int bx, int by, char* sm) {
    const int tid = threadIdx.x, wid = tid >> 5, lane = tid & 31;
    const uint32_t smb = smem_u32(sm);
    const int rowb = by * 128, colb = bx * 128;
    const int warp_m = wid >> 2, warp_n = wid & 3;
    const int r = tid >> 3, sgi = tid & 7;
    const uint4* Ab = A + (size_t)rowb * 256;
    const uint4* Bb = B + (size_t)colb * 256;

    const int arow_l = (lane & 7) + ((lane >> 3) & 1) * 8;
    const int acol_l = (lane >> 4) * 16;
    const int brow_l = (lane & 7) + (lane >> 4) * 8;
    const int bcol_l = ((lane >> 3) & 1) * 16;

    float acc[4][4][4];
    #pragma unroll
    for (int mt = 0; mt < 4; mt++)
        #pragma unroll
        for (int nt = 0; nt < 4; nt++)
            #pragma unroll
            for (int e = 0; e < 4; e++) acc[mt][nt][e] = 0.f;

    #pragma unroll
    for (int c0 = 0; c0 < 2; c0++) {
        uint32_t stp = smb + c0 * GSTAGE_B;
        #pragma unroll
        for (int it = 0; it < 4; it++) {
            int rr = r + it * 32;
            uint32_t so = SWZ128(rr * 128 + sgi * 16);
            CP_ASYNC16(stp + so,         (const void*)(Ab + (size_t)rr * 256 + c0 * 8 + sgi));
            CP_ASYNC16(stp + 16384 + so, (const void*)(Bb + (size_t)rr * 256 + c0 * 8 + sgi));
        }
        CP_COMMIT();
    }
    CP_WAIT1();
    __syncthreads();

    for (int c = 0; c < 32; c++) {
        uint32_t stb = smb + (c % GSTAGES) * GSTAGE_B;
        if (c + 2 < 32) {
            uint32_t nstb = smb + ((c + 2) % GSTAGES) * GSTAGE_B;
            #pragma unroll
            for (int it = 0; it < 4; it++) {
                int rr = r + it * 32;
                uint32_t so = SWZ128(rr * 128 + sgi * 16);
                CP_ASYNC16(nstb + so,         (const void*)(Ab + (size_t)rr * 256 + (c + 2) * 8 + sgi));
                CP_ASYNC16(nstb + 16384 + so, (const void*)(Bb + (size_t)rr * 256 + (c + 2) * 8 + sgi));
            }
            CP_COMMIT();
        }

        #pragma unroll
        for (int s = 0; s < 2; s++) {
            const int kbh = s * 32, kbl = 64 + s * 32;
            uint32_t bh[2][4], bl[2][4];
            #pragma unroll
            for (int p = 0; p < 2; p++) {
                int bb = 16384 + (warp_n * 32 + p * 16 + brow_l) * 128 + bcol_l;
                LDSM4(bh[p], stb + SWZ128(bb + kbh));
                LDSM4(bl[p], stb + SWZ128(bb + kbl));
            }
            #pragma unroll
            for (int mt = 0; mt < 4; mt++) {
                uint32_t ah[4], al[4];
                int ab = (warp_m * 64 + mt * 16 + arow_l) * 128 + acol_l;
                LDSM4(ah, stb + SWZ128(ab + kbh));
                LDSM4(al, stb + SWZ128(ab + kbl));
                #pragma unroll
                for (int nt = 0; nt < 4; nt++) {
                    MMA16816(acc[mt][nt], ah, &bh[nt >> 1][(nt & 1) * 2]);
                    MMA16816(acc[mt][nt], ah, &bl[nt >> 1][(nt & 1) * 2]);
                    MMA16816(acc[mt][nt], al, &bh[nt >> 1][(nt & 1) * 2]);
                }
            }
        }
        if (c + 1 < 32) {
            if (c + 2 < 32) { CP_WAIT1(); } else { CP_WAIT0(); }
        }
        __syncthreads();
    }

    #pragma unroll
    for (int mt = 0; mt < 4; mt++) {
        #pragma unroll
        for (int hf = 0; hf < 2; hf++) {
            int r0 = warp_m * 64 + mt * 16 + hf * 8 + (lane >> 2);
            #pragma unroll
            for (int nt = 0; nt < 4; nt++) {
                int cl = warp_n * 32 + nt * 8 + (lane & 3) * 2;
                if (PACK) {
                    float rr0, rr1;
                    unsigned int hi = bfpack2(acc[mt][nt][hf * 2], acc[mt][nt][hf * 2 + 1], rr0, rr1);
                    unsigned int lo = bfpack2n(rr0, rr1);
                    int wl = (cl >> 5) * 32 + ((cl & 31) >> 1);
                    *(unsigned int*)(sm + r0 * STAGE_ROWB + wl * 4)      = hi;
                    *(unsigned int*)(sm + r0 * STAGE_ROWB + wl * 4 + 64) = lo;
                } else {
                    *(float2*)(sm + r0 * STAGE_ROWB + cl * 4) =
                        make_float2(acc[mt][nt][hf * 2], acc[mt][nt][hf * 2 + 1]);
                }
            }
        }
    }
    __syncthreads();
    char* Cb = (char*)Cout;
    #pragma unroll
    for (int i = 0; i < 16; i++) {
        int idx = tid + i * 256;
        int row = idx >> 5, ch = idx & 31;
        uint4 v = *(uint4*)(sm + row * STAGE_ROWB + ch * 16);
        *(uint4*)(Cb + ((size_t)(rowb + row) * N + colb + ch * 4) * 4) = v;
    }
}

__global__ __launch_bounds__(256, 2) void k_gemm_qkv(const uint4* __restrict__ Aq,
                                                     const uint4* __restrict__ Bq,
                                                     unsigned int* __restrict__ Cq,
                                                     const uint4* __restrict__ Akv,
                                                     const uint4* __restrict__ Bkv,
                                                     unsigned int* __restrict__ Ckv) {
    extern __shared__ __align__(1024) char sm[];
    int bid = blockIdx.x;
    if (bid < 256) {
        gemm_body<true>(Aq, Bq, Cq, INNER, bid & 7, bid >> 3, sm);
    } else {
        int b2 = bid - 256;
        gemm_body<true>(Akv, Bkv, Ckv, 2 * INNER, b2 & 15, b2 >> 4, sm);
    }
}

__global__ __launch_bounds__(256, 2) void k_gemm_out(const uint4* __restrict__ A,
                                                     const uint4* __restrict__ B,
                                                     float* __restrict__ C) {
    extern __shared__ __align__(1024) char sm[];
    int bid = blockIdx.x;
    gemm_body<false>(A, B, C, DIM_, bid & 7, bid >> 3, sm);
}

// ------------------- attention (Q-in-regs, split K/V waits) -----------------
// grid (64 q-tiles, 16 heads); block 128 (4 warps, M-split 16 rows/warp).
// QK logits arrive pre-scaled into exp2 domain (scale folded into Wq).
// SMEM: K 2x16384 @0 | V 2x16384 @32768 | Ts @65536.
#define ATT_K    0
#define ATT_V    32768
#define ATT_TS   65536
#define ATT_SMEM (ATT_TS + 256)

__device__ __forceinline__ void attn_fill(uint32_t smb, const unsigned int* __restrict__ kvp,
                                          int kbase, int h, int tid) {
    #pragma unroll
    for (int it = 0; it < 16; it++) {
        int t = tid + it * 128;
        int row = t >> 4, rest = t & 15;
        int panel = rest >> 3, q4 = rest & 7;
        uint32_t so = SWZ128(row * 128 + q4 * 16);
        CP_ASYNC16(smb + ATT_K + panel * 16384 + so,
                   (const void*)&kvp[(size_t)(kbase + row) * 2048 + (h * 2 + panel) * 32 + q4 * 4]);
    }
    CP_COMMIT();
    #pragma unroll
    for (int it = 0; it < 16; it++) {
        int t = tid + it * 128;
        int row = t >> 4, rest = t & 15;
        int panel = rest >> 3, q4 = rest & 7;
        uint32_t so = SWZ128(row * 128 + q4 * 16);
        CP_ASYNC16(smb + ATT_V + panel * 16384 + so,
                   (const void*)&kvp[(size_t)(kbase + row) * 2048 + (32 + h * 2 + panel) * 32 + q4 * 4]);
    }
    CP_COMMIT();
}

__global__ __launch_bounds__(128, 3) void k_attn(const unsigned int* __restrict__ qp,
                                                 const unsigned int* __restrict__ kvp,
                                                 const int* __restrict__ tt,
                                                 unsigned int* __restrict__ aop) {
    extern __shared__ __align__(1024) char sm[];
    const uint32_t smb = smem_u32(sm);
    const int tid = threadIdx.x, w = tid >> 5, lane = tid & 31;
    const int tile = blockIdx.x, h = blockIdx.y;
    const int gq0 = tile * 64;
    const int b = gq0 >> 11;

    const int brow_l = (lane & 7) + (lane >> 4) * 8;
    const int bcol_l = ((lane >> 3) & 1) * 16;

    int* Ts = (int*)(sm + ATT_TS);
    if (tid < 64) Ts[tid] = tt[gq0 + tid];

    const int rr0 = w * 16 + (lane >> 2);
    const int rr8 = rr0 + 8;

    __syncthreads();   // Ts visible
    int c0 = Ts[0] < 1 ? 1 : Ts[0];
    int c1 = Ts[63];

    if (c0 <= c1)
        attn_fill(smb, kvp, b * (TMEDIA * MTOK) + (c0 - 1) * MTOK, h, tid);

    // ---- Q fragments direct from packed global: qh/ql[kstep][a0..a3]
    uint32_t qh[4][4], ql[4][4];
    {
        const unsigned int* q0p = qp + (size_t)(gq0 + rr0) * 1024 + h * 64;
        const unsigned int* q8p = qp + (size_t)(gq0 + rr8) * 1024 + h * 64;
        #pragma unroll
        for (int ks = 0; ks < 4; ks++) {
            int off = (ks >> 1) * 32 + (ks & 1) * 8 + (lane & 3);
            qh[ks][0] = q0p[off];      qh[ks][1] = q8p[off];
            qh[ks][2] = q0p[off + 4];  qh[ks][3] = q8p[off + 4];
            ql[ks][0] = q0p[off + 16]; ql[ks][1] = q8p[off + 16];
            ql[ks][2] = q0p[off + 20]; ql[ks][3] = q8p[off + 20];
        }
    }

    #pragma unroll
    for (int it = 0; it < 8; it++) {
        int slot = tid + it * 128;
        int row = slot >> 4, w4 = slot & 15;
        if (Ts[row] == 0)
            *(uint4*)&aop[(size_t)(gq0 + row) * 1024 + h * 64 + w4 * 4] =
                make_uint4(0, 0, 0, 0);
    }

    const int t_midx = lane >> 3, t_lrow = lane & 7;
    const int t_tok_off = (t_midx & 1) * 8 + t_lrow;
    const int t_seg     = (t_midx >> 1) * 16;

    bool first = true;
    for (int c = c0; c <= c1; c++) {
        float o[8][4];
        #pragma unroll
        for (int dt = 0; dt < 8; dt++)
            #pragma unroll
            for (int e = 0; e < 4; e++) o[dt][e] = 0.f;
        float pm0 = -1e30f, pm1 = -1e30f, l0 = 0.f, l1 = 0.f;

        #pragma unroll
        for (int hx = 0; hx < 2; hx++) {
            const int kbase = b * (TMEDIA * MTOK) + (c - 1) * MTOK + hx * 128;
            if (!first) {
                __syncthreads();
                attn_fill(smb, kvp, kbase, h, tid);
            }
            first = false;
            CP_WAIT1();            // K complete (V still in flight)
            __syncthreads();

            // ---- QK^T: M=16, N=128, K=64 (split x3), Q from regs
            float acc[16][4];
            #pragma unroll
            for (int nt = 0; nt < 16; nt++)
                #pragma unroll
                for (int e = 0; e < 4; e++) acc[nt][e] = 0.f;

            #pragma unroll
            for (int cc = 0; cc < 2; cc++) {
                uint32_t kb = smb + ATT_K + cc * 16384;
                #pragma unroll
                for (int s = 0; s < 2; s++) {
                    const int kstep = cc * 2 + s;
                    const int kbh = s * 32, kbl = 64 + s * 32;
                    #pragma unroll
                    for (int p4 = 0; p4 < 2; p4++) {
                        uint32_t bh[4][4], bl[4][4];
                        #pragma unroll
                        for (int p = 0; p < 4; p++) {
                            int bb = ((p4 * 4 + p) * 16 + brow_l) * 128 + bcol_l;
                            LDSM4(bh[p], kb + SWZ128(bb + kbh));
                            LDSM4(bl[p], kb + SWZ128(bb + kbl));
                        }
                        #pragma unroll
                        for (int nt = 0; nt < 8; nt++) {
                            float* d = acc[p4 * 8 + nt];
                            MMA16816(d, qh[kstep], &bh[nt >> 1][(nt & 1) * 2]);
                            MMA16816(d, qh[kstep], &bl[nt >> 1][(nt & 1) * 2]);
                            MMA16816(d, ql[kstep], &bh[nt >> 1][(nt & 1) * 2]);
                        }
                    }
                }
            }

            // ---- online softmax (logits already in exp2 domain)
            float m0 = -1e30f, m1 = -1e30f;
            #pragma unroll
            for (int nt = 0; nt < 16; nt++) {
                m0 = fmaxf(m0, fmaxf(acc[nt][0], acc[nt][1]));
                m1 = fmaxf(m1, fmaxf(acc[nt][2], acc[nt][3]));
            }
            m0 = fmaxf(m0, __shfl_xor_sync(0xffffffffu, m0, 1));
            m0 = fmaxf(m0, __shfl_xor_sync(0xffffffffu, m0, 2));
            m1 = fmaxf(m1, __shfl_xor_sync(0xffffffffu, m1, 1));
            m1 = fmaxf(m1, __shfl_xor_sync(0xffffffffu, m1, 2));
            float n0 = fmaxf(pm0, m0), n1 = fmaxf(pm1, m1);
            float a0 = ex2f_(pm0 - n0), a1 = ex2f_(pm1 - n1);
            #pragma unroll
            for (int dt = 0; dt < 8; dt++) {
                o[dt][0] *= a0; o[dt][1] *= a0;
                o[dt][2] *= a1; o[dt][3] *= a1;
            }
            float s0 = 0.f, s1 = 0.f;
            #pragma unroll
            for (int nt = 0; nt < 16; nt++) {
                float e0 = ex2f_(acc[nt][0] - n0), e1 = ex2f_(acc[nt][1] - n0);
                float e2 = ex2f_(acc[nt][2] - n1), e3 = ex2f_(acc[nt][3] - n1);
                acc[nt][0] = e0; acc[nt][1] = e1; acc[nt][2] = e2; acc[nt][3] = e3;
                s0 += e0 + e1; s1 += e2 + e3;
            }
            s0 += __shfl_xor_sync(0xffffffffu, s0, 1);
            s0 += __shfl_xor_sync(0xffffffffu, s0, 2);
            s1 += __shfl_xor_sync(0xffffffffu, s1, 1);
            s1 += __shfl_xor_sync(0xffffffffu, s1, 2);
            l0 = l0 * a0 + s0; l1 = l1 * a1 + s1;
            pm0 = n0; pm1 = n1;

            // ---- V ready, then PV (P packed in regs; V frags via ldmatrix.trans)
            CP_WAIT0();
            __syncthreads();

            #pragma unroll
            for (int ks = 0; ks < 8; ks++) {
                uint32_t aph[4], apl[4];
                float q0, q1;
                aph[0] = bfpack2(acc[2 * ks][0],     acc[2 * ks][1],     q0, q1);
                apl[0] = bfpack2n(q0, q1);
                aph[1] = bfpack2(acc[2 * ks][2],     acc[2 * ks][3],     q0, q1);
                apl[1] = bfpack2n(q0, q1);
                aph[2] = bfpack2(acc[2 * ks + 1][0], acc[2 * ks + 1][1], q0, q1);
                apl[2] = bfpack2n(q0, q1);
                aph[3] = bfpack2(acc[2 * ks + 1][2], acc[2 * ks + 1][3], q0, q1);
                apl[3] = bfpack2n(q0, q1);

                int token = ks * 16 + t_tok_off;
                #pragma unroll
                for (int d16 = 0; d16 < 4; d16++) {
                    uint32_t vb = smb + ATT_V + (d16 >> 1) * 16384;
                    int boff = (d16 & 1) * 32 + t_seg;
                    uint32_t bvh4[4], bvl4[4];
                    LDSM4T(bvh4, vb + SWZ128(token * 128 + boff));
                    LDSM4T(bvl4, vb + SWZ128(token * 128 + 64 + boff));
                    #pragma unroll
                    for (int dt2 = 0; dt2 < 2; dt2++) {
                        int dt = d16 * 2 + dt2;
                        MMA16816(o[dt], aph, &bvh4[dt2 * 2]);
                        MMA16816(o[dt], aph, &bvl4[dt2 * 2]);
                        MMA16816(o[dt], apl, &bvh4[dt2 * 2]);
                    }
                }
            }
        }

        // ---- store rows belonging to this chunk (deferred normalization)
        float inv0 = 1.0f / l0, inv1 = 1.0f / l1;
        bool st0 = (Ts[rr0] == c), st1 = (Ts[rr8] == c);
        if (st0 || st1) {
            #pragma unroll
            for (int dt = 0; dt < 8; dt++) {
                int d2 = dt * 8 + (lane & 3) * 2;
                int wofs = (h * 2 + (d2 >> 5)) * 32 + ((d2 & 31) >> 1);
                if (st0) {
                    float q0, q1;
                    unsigned int hi = bfpack2(o[dt][0] * inv0, o[dt][1] * inv0, q0, q1);
                    unsigned int lo = bfpack2n(q0, q1);
                    size_t idx = (size_t)(gq0 + rr0) * 1024 + wofs;
                    aop[idx] = hi; aop[idx + 16] = lo;
                }
                if (st1) {
                    float q0, q1;
                    unsigned int hi = bfpack2(o[dt][2] * inv1, o[dt][3] * inv1, q0, q1);
                    unsigned int lo = bfpack2n(q0, q1);
                    size_t idx = (size_t)(gq0 + rr8) * 1024 + wofs;
                    aop[idx] = hi; aop[idx + 16] = lo;
                }
            }
        }
    }
}

// ------------------------------- launcher ---------------------------------
extern "C" void kernel_launch(void* const* d_in, const int* in_sizes, int n_in,
                              void* d_out, int out_size) {
    const float*         x     = (const float*)d_in[0];
    const float*         media = (const float*)d_in[1];
    const unsigned char* locs  = (const unsigned char*)d_in[2];
    const float*         gamma = (const float*)d_in[3];
    const float*         beta  = (const float*)d_in[4];
    const float*         Wq    = (const float*)d_in[5];
    const float*         Wkv   = (const float*)d_in[6];
    const float*         Wout  = (const float*)d_in[7];
    float*               out   = (float*)d_out;

    unsigned int *xnp, *medp, *aop, *wqt, *wkvt, *woutt, *qp, *kvp;
    int *ttb;
    cudaGetSymbolAddress((void**)&xnp,   g_xnp);
    cudaGetSymbolAddress((void**)&medp,  g_medp);
    cudaGetSymbolAddress((void**)&aop,   g_aop);
    cudaGetSymbolAddress((void**)&wqt,   g_wqt);
    cudaGetSymbolAddress((void**)&wkvt,  g_wkvt);
    cudaGetSymbolAddress((void**)&woutt, g_woutt);
    cudaGetSymbolAddress((void**)&qp,    g_qp);
    cudaGetSymbolAddress((void**)&kvp,   g_kvp);
    cudaGetSymbolAddress((void**)&ttb,   g_tt);

    static bool attr_done = false;
    if (!attr_done) {
        cudaFuncSetAttribute(k_gemm_qkv, cudaFuncAttributeMaxDynamicSharedMemorySize, GSMEM);
        cudaFuncSetAttribute(k_gemm_out, cudaFuncAttributeMaxDynamicSharedMemorySize, GSMEM);
        cudaFuncSetAttribute(k_attn, cudaFuncAttributeMaxDynamicSharedMemorySize, ATT_SMEM);
        attr_done = true;
    }

    // 4 launches.
    k_pack_all<<<NROWS + KVROWS + 4096 + 1, 256>>>(x, gamma, beta, media, Wq, Wkv, Wout,
                                                   locs, xnp, medp, wqt, wkvt, woutt, ttb);
    k_gemm_qkv<<<768, 256, GSMEM>>>((const uint4*)xnp,  (const uint4*)wqt,  qp,
                                    (const uint4*)medp, (const uint4*)wkvt, kvp);
    k_attn<<<dim3(64, HEADS), 128, ATT_SMEM>>>(qp, kvp, ttb, aop);
    k_gemm_out<<<256, 256, GSMEM>>>((const uint4*)aop, (const uint4*)woutt, out);
}